// round 12
// baseline (speedup 1.0000x reference)
#include <cuda_runtime.h>
#include <cuda_bf16.h>
#include <math.h>
#include <stdint.h>

#define NN   20000
#define NNP  20032
#define EE   320000
#define DD   128
#define DEH  64
#define NTILES (EE / 128)   // 2500
#define GRID_MLP 148
#define NB   128            // nodes per k_final CTA

// ---------------- scratch (device globals; no allocation allowed) ----------------
__device__ float g_h[NN * DD];                 // node_fc output h
__device__ float g_acc[(size_t)NNP * 512];     // per-node [P | Q0 | Q1 | Q2] (pre-scaled)
__device__ float g_za[NNP];                    // sum exp(a) per dst (mask)
__device__ float g_Ct_hi[4 * DD * DD];         // folded C, transposed [ph][out][k], tf32 hi
__device__ float g_Ct_lo[4 * DD * DD];         // tf32 lo residual
__device__ float g_Wt_hi[DD * DD];             // node_fc W transposed [out][k], tf32 hi
__device__ float g_Wt_lo[DD * DD];             // tf32 lo residual
__device__ float g_eg4f[(size_t)EE * 4];       // [e] = {eg0, eg1, eg2, -}
__device__ float g_B[384 * 64];                // folded MLP weights Gᵀ (tf32-rounded fp32)
__device__ float g_bb[384];                    // folded bias bb1
__device__ int   g_deg[NN];
__device__ int   g_off[NN];
__device__ int   g_cur[NN];
__device__ int2  g_epack[EE];                  // (src, e) sorted by dst

__device__ __forceinline__ float sigmoidf_(float x) { return 1.f / (1.f + __expf(-x)); }

__device__ __forceinline__ uint32_t smem_to_u32(const void* p) {
    uint32_t a;
    asm("{ .reg .u64 t; cvta.to.shared.u64 t, %1; cvt.u32.u64 %0, t; }" : "=r"(a) : "l"(p));
    return a;
}
__device__ __forceinline__ uint32_t tf32_rna(float x) {
    uint32_t r; asm("cvt.rna.tf32.f32 %0, %1;" : "=r"(r) : "f"(x)); return r;
}
__device__ __forceinline__ float tf32f(float x) { return __uint_as_float(tf32_rna(x)); }
__device__ __forceinline__ void mma_tf32(float& c0, float& c1, float& c2, float& c3,
                                         uint32_t a0, uint32_t a1, uint32_t a2, uint32_t a3,
                                         uint32_t b0, uint32_t b1) {
    asm volatile("mma.sync.aligned.m16n8k8.row.col.f32.tf32.tf32.f32 "
                 "{%0,%1,%2,%3}, {%4,%5,%6,%7}, {%8,%9}, {%0,%1,%2,%3};"
                 : "+f"(c0), "+f"(c1), "+f"(c2), "+f"(c3)
                 : "r"(a0), "r"(a1), "r"(a2), "r"(a3), "r"(b0), "r"(b1));
}
__device__ __forceinline__ void cp16(float* dst_smem, const float* src) {
    uint32_t d = smem_to_u32(dst_smem);
    asm volatile("cp.async.ca.shared.global [%0], [%1], 16;" :: "r"(d), "l"(src));
}
#define CP_COMMIT asm volatile("cp.async.commit_group;" ::: "memory")
#define CP_WAIT2  asm volatile("cp.async.wait_group 2;"  ::: "memory")
#define CP_WAIT0  asm volatile("cp.async.wait_group 0;"  ::: "memory")

// ---------------- prepW (critical path, tiny): node_fc weight transpose + split ----------------
__global__ void __launch_bounds__(128) k_prepW(const float* __restrict__ nfcW)
{
    int k = blockIdx.x, c = threadIdx.x;
    float v = nfcW[k * DD + c];
    float hi = tf32f(v);
    g_Wt_hi[c * DD + k] = hi;
    g_Wt_lo[c * DD + k] = tf32f(v - hi);
}

// ---------------- prepF (side stream): fold G = efcW @ W1 (tf32) + bias ----------------
__global__ void __launch_bounds__(128) k_prepF(const float* __restrict__ efcW,
                                               const float* __restrict__ efcb,
                                               const float* __restrict__ W1,
                                               const float* __restrict__ b1)
{
    __shared__ float sW[4096];   // transposed efcW: sW[fp*64 + k]
    int tid = threadIdx.x;
    for (int i = tid; i < 4096; i += 128) {
        int k = i >> 6, fp = i & 63;
        sW[fp * 64 + k] = efcW[i];
    }
    __syncthreads();
    int half = tid >> 6;
    int k = tid & 63;
    int n = blockIdx.x * 2 + half;
    int m = n >> 7, f = n & 127;
    float acc = 0.f;
    float bacc = b1[n];
    #pragma unroll 4
    for (int fp = 0; fp < DEH; fp++) {
        float w1v = __ldg(&W1[(m * DEH + fp) * DD + f]);
        acc += sW[fp * 64 + k] * w1v;
        bacc += __ldg(&efcb[fp]) * w1v;
    }
    g_B[n * 64 + k] = tf32f(acc);
    if (k == 0) g_bb[n] = bacc;
}

// ---------------- combine (side stream): C0 = Wsum@U_top, Cm = W_m@U_bot ----------------
__global__ void __launch_bounds__(128) k_combine(const float* __restrict__ natt,
                                                 const float* __restrict__ relW,
                                                 const float* __restrict__ outW)
{
    __shared__ float row[DD];
    int i = blockIdx.x >> 7;          // phase 0..3
    int d = blockIdx.x & 127;         // k
    int c = threadIdx.x;              // output
    if (i == 0)
        row[c] = natt[d * DD + c] + natt[DD * DD + d * DD + c] + natt[2 * DD * DD + d * DD + c];
    else
        row[c] = relW[(i - 1) * DD * DD + d * DD + c];
    __syncthreads();
    const float* U = (i == 0) ? outW : outW + DD * DD;
    float acc = 0.f;
    #pragma unroll 8
    for (int f = 0; f < DD; f++) acc += row[f] * U[f * DD + c];
    float hi = tf32f(acc);
    g_Ct_hi[i * DD * DD + c * DD + d] = hi;
    g_Ct_lo[i * DD * DD + c * DD + d] = tf32f(acc - hi);
}

// ---------------- kernel A: h = nf @ node_fc_W + b  (tf32 mma, 3-pass compensated) ----------------
#define NF_STRIDE 132
#define SMEM_NFC ((16896 * 2 + 128) * 4)

__global__ void __launch_bounds__(256, 1) k_node_fc(const float* __restrict__ nf,
                                                    const float* __restrict__ b)
{
    extern __shared__ float sm[];
    float* Ws  = sm;
    float* As  = sm + 16896;
    float* bsm = sm + 2 * 16896;

    int tid = threadIdx.x;
    int w = tid >> 5, lane = tid & 31;
    int g = lane >> 2, tig = lane & 3;
    int nbase = blockIdx.x * 128;
    if (tid < 128) bsm[tid] = b[tid];

    float c[16][4];
    #pragma unroll
    for (int i = 0; i < 16; i++) { c[i][0]=0.f; c[i][1]=0.f; c[i][2]=0.f; c[i][3]=0.f; }

    #pragma unroll
    for (int pass = 0; pass < 3; pass++) {
        __syncthreads();
        if (pass != 1) {
            bool lo = (pass == 2);
            for (int q = tid; q < 4096; q += 256) {
                int n = q >> 5, kq = q & 31;
                int gn = nbase + n;
                float4 v = make_float4(0.f,0.f,0.f,0.f);
                if (gn < NN) v = *(const float4*)&nf[(size_t)gn * DD + kq * 4];
                float4 o;
                if (!lo) o = make_float4(tf32f(v.x), tf32f(v.y), tf32f(v.z), tf32f(v.w));
                else     o = make_float4(tf32f(v.x - tf32f(v.x)), tf32f(v.y - tf32f(v.y)),
                                         tf32f(v.z - tf32f(v.z)), tf32f(v.w - tf32f(v.w)));
                *(float4*)&As[n * NF_STRIDE + kq * 4] = o;
            }
        }
        const float* Wsrc = (pass == 1) ? g_Wt_lo : g_Wt_hi;
        for (int q = tid; q < 4096; q += 256) {
            int rr = q >> 5, kq = q & 31;
            cp16(&Ws[rr * NF_STRIDE + kq * 4], &Wsrc[rr * DD + kq * 4]);
        }
        CP_COMMIT; CP_WAIT0;
        __syncthreads();

        uint32_t a0[16], a1[16], a2[16], a3[16];
        const float* w0 = &Ws[(w * 16 + g) * NF_STRIDE];
        const float* w1 = &Ws[(w * 16 + 8 + g) * NF_STRIDE];
        #pragma unroll
        for (int kk = 0; kk < 16; kk++) {
            a0[kk] = __float_as_uint(w0[kk * 8 + tig]);
            a2[kk] = __float_as_uint(w0[kk * 8 + tig + 4]);
            a1[kk] = __float_as_uint(w1[kk * 8 + tig]);
            a3[kk] = __float_as_uint(w1[kk * 8 + tig + 4]);
        }
        #pragma unroll
        for (int nt = 0; nt < 16; nt++) {
            const float* bp = &As[(nt * 8 + g) * NF_STRIDE];
            #pragma unroll
            for (int kk = 0; kk < 16; kk++) {
                uint32_t b0 = __float_as_uint(bp[kk * 8 + tig]);
                uint32_t b1 = __float_as_uint(bp[kk * 8 + tig + 4]);
                mma_tf32(c[nt][0], c[nt][1], c[nt][2], c[nt][3],
                         a0[kk], a1[kk], a2[kk], a3[kk], b0, b1);
            }
        }
    }

    __syncthreads();
    #pragma unroll
    for (int nt = 0; nt < 16; nt++) {
        int n0 = nt * 8 + tig * 2;
        As[n0 * NF_STRIDE + w * 16 + g]           = c[nt][0];
        As[(n0 + 1) * NF_STRIDE + w * 16 + g]     = c[nt][1];
        As[n0 * NF_STRIDE + w * 16 + 8 + g]       = c[nt][2];
        As[(n0 + 1) * NF_STRIDE + w * 16 + 8 + g] = c[nt][3];
    }
    __syncthreads();
    for (int q = tid; q < 4096; q += 256) {
        int n = q >> 5, kq = q & 31;
        int gn = nbase + n;
        if (gn < NN) {
            float4 v = *(const float4*)&As[n * NF_STRIDE + kq * 4];
            float4 bb = *(const float4*)&bsm[kq * 4];
            *(float4*)&g_h[(size_t)gn * DD + kq * 4] =
                make_float4(v.x + bb.x, v.y + bb.y, v.z + bb.z, v.w + bb.w);
        }
    }
}

// ---------------- CSR build ----------------
__global__ void k_hist(const int* __restrict__ dst)
{
    int e = blockIdx.x * 256 + threadIdx.x;
    if (e < EE) atomicAdd(&g_deg[dst[e]], 1);
}

__global__ void __launch_bounds__(1024) k_scan()
{
    int tid = threadIdx.x;
    int lane = tid & 31, w = tid >> 5;
    int base = tid * 20;
    int loc[20]; int s = 0;
    #pragma unroll
    for (int j = 0; j < 20; j++) {
        int n = base + j;
        int d = (n < NN) ? g_deg[n] : 0;
        loc[j] = s; s += d;
    }
    int v = s;
    #pragma unroll
    for (int off = 1; off < 32; off <<= 1) {
        int u = __shfl_up_sync(0xffffffffu, v, off);
        if (lane >= off) v += u;
    }
    __shared__ int wsum[32];
    if (lane == 31) wsum[w] = v;
    __syncthreads();
    if (w == 0) {
        int t = wsum[lane];
        #pragma unroll
        for (int off = 1; off < 32; off <<= 1) {
            int u = __shfl_up_sync(0xffffffffu, t, off);
            if (lane >= off) t += u;
        }
        wsum[lane] = t;
    }
    __syncthreads();
    int excl = v - s + (w > 0 ? wsum[w - 1] : 0);
    #pragma unroll
    for (int j = 0; j < 20; j++) {
        int n = base + j;
        if (n < NN) { int o = excl + loc[j]; g_off[n] = o; g_cur[n] = o; }
    }
}

__global__ void k_fill(const int* __restrict__ src, const int* __restrict__ dst)
{
    int e = blockIdx.x * 256 + threadIdx.x;
    if (e < EE) {
        int d = dst[e];
        int pos = atomicAdd(&g_cur[d], 1);
        g_epack[pos] = make_int2(src[e], e);
    }
}

// ---------------- kernel B: tensor-core (mma.sync tf32) edge MLP -> g_eg4f[.xyz] ----------------
// 3-stage cp.async pipeline; B pair-packed so each LDS.128 feeds 2 mmas
#define BP_STRIDE 72
#define A_STRIDE  68
#define A_BUF_F   (128 * A_STRIDE)          // 8704 floats
#define OFF_EPI   27648
#define OFF_A     (27648 + 768)
#define SMEM_MLP  ((27648 + 768 + 3 * A_BUF_F) * 4)

__global__ void __launch_bounds__(768, 1) k_mlp(const float* __restrict__ ef,
                                                const float* __restrict__ W2,
                                                const float* __restrict__ b2)
{
    extern __shared__ float sm[];
    float*  Bp  = sm;
    float2* epi = (float2*)(sm + OFF_EPI);
    float*  As  = sm + OFF_A;

    int tid = threadIdx.x;
    int wid = tid >> 5, lane = tid & 31;
    int g = lane >> 2, tig = lane & 3;
    int m = wid >> 3;          // head 0..2
    int r = wid & 7;           // row slice 0..7
    int rowbase = r * 16;

    // quad-packed B: float4 at [n*72 + (kk>>1)*16 + (t&3)*4] =
    //   {B[n][2p*8+t], B[n][2p*8+t+4], B[n][(2p+1)*8+t], B[n][(2p+1)*8+t+4]}
    for (int i = tid; i < 384 * 64; i += 768) {
        int n = i >> 6, k = i & 63;
        int kk = k >> 3, t = k & 7;
        int pos = n * BP_STRIDE + (kk >> 1) * 16 + (t & 3) * 4 + (kk & 1) * 2 + (t >> 2);
        Bp[pos] = g_B[i];
    }
    if (tid < 384) epi[tid] = make_float2(g_bb[tid], __ldg(W2 + tid));
    __syncthreads();

    float b2m = __ldg(b2 + m);

    int t0 = blockIdx.x;
    // prologue: stages 0 and 1
    #pragma unroll
    for (int p = 0; p < 2; p++) {
        int tp = t0 + p * GRID_MLP;
        if (tp < NTILES) {
            const float* srcb = ef + (size_t)tp * 8192;
            float* dstb = As + p * A_BUF_F;
            for (int c = tid; c < 2048; c += 768)
                cp16(dstb + (c >> 4) * A_STRIDE + (c & 15) * 4, srcb + c * 4);
        }
        CP_COMMIT;
    }

    int buf = 0;
    for (int t = t0; t < NTILES; t += GRID_MLP) {
        int tn = t + 2 * GRID_MLP;
        if (tn < NTILES) {
            const float* srcb = ef + (size_t)tn * 8192;
            int slot = buf + 2; if (slot >= 3) slot -= 3;
            float* dstb = As + slot * A_BUF_F;
            for (int c = tid; c < 2048; c += 768)
                cp16(dstb + (c >> 4) * A_STRIDE + (c & 15) * 4, srcb + c * 4);
        }
        CP_COMMIT;
        CP_WAIT2;              // oldest group (current buf) complete
        __syncthreads();

        const float* A = As + buf * A_BUF_F;
        const float* r0p = A + (rowbase + g) * A_STRIDE;
        const float* r1p = A + (rowbase + g + 8) * A_STRIDE;
        uint32_t a0[8], a1[8], a2[8], a3[8];
        #pragma unroll
        for (int kk = 0; kk < 8; kk++) {
            a0[kk] = __float_as_uint(r0p[kk * 8 + tig]);
            a2[kk] = __float_as_uint(r0p[kk * 8 + tig + 4]);
            a1[kk] = __float_as_uint(r1p[kk * 8 + tig]);
            a3[kk] = __float_as_uint(r1p[kk * 8 + tig + 4]);
        }

        float p0 = 0.f, p1 = 0.f;
        #pragma unroll 4
        for (int nt = 0; nt < 16; nt++) {
            int n0 = m * 128 + nt * 8;
            float c0 = 0.f, c1 = 0.f, c2 = 0.f, c3 = 0.f;
            const float4* bp4 = (const float4*)(Bp + (n0 + g) * BP_STRIDE) + tig;
            #pragma unroll
            for (int kkp = 0; kkp < 4; kkp++) {
                float4 bv = bp4[kkp * 4];
                int ke = 2 * kkp, ko = 2 * kkp + 1;
                mma_tf32(c0, c1, c2, c3, a0[ke], a1[ke], a2[ke], a3[ke],
                         __float_as_uint(bv.x), __float_as_uint(bv.y));
                mma_tf32(c0, c1, c2, c3, a0[ko], a1[ko], a2[ko], a3[ko],
                         __float_as_uint(bv.z), __float_as_uint(bv.w));
            }
            float2 e0 = epi[n0 + 2 * tig];
            float2 e1 = epi[n0 + 2 * tig + 1];
            p0 += fmaxf(c0 + e0.x, 0.f) * e0.y + fmaxf(c1 + e1.x, 0.f) * e1.y;
            p1 += fmaxf(c2 + e0.x, 0.f) * e0.y + fmaxf(c3 + e1.x, 0.f) * e1.y;
        }
        #pragma unroll
        for (int off = 1; off <= 2; off <<= 1) {
            p0 += __shfl_xor_sync(0xffffffffu, p0, off);
            p1 += __shfl_xor_sync(0xffffffffu, p1, off);
        }
        if (tig == 0) {
            int e = t * 128 + rowbase + g;
            g_eg4f[(size_t)(e)     * 4 + m] = __expf(sigmoidf_(p0 + b2m));
            g_eg4f[(size_t)(e + 8) * 4 + m] = __expf(sigmoidf_(p1 + b2m));
        }
        __syncthreads();
        buf++; if (buf >= 3) buf = 0;
    }
}

// ---------------- kernel C: gather (warp per dst node; batched epack via shfl) ----------------
__global__ void __launch_bounds__(256) k_gather()
{
    int n = (blockIdx.x * 256 + threadIdx.x) >> 5;
    int lane = threadIdx.x & 31;
    if (n >= NN) return;

    int off = g_off[n];
    int deg = g_deg[n];
    float4 hd = *(const float4*)&g_h[(size_t)n * DD + lane * 4];

    float4 aP = make_float4(0.f,0.f,0.f,0.f), q0 = aP, q1 = aP, q2 = aP;
    float za = 0.f, z0 = 0.f, z1 = 0.f, z2 = 0.f;

    int j = 0;
    while (j < deg) {
        int cnt = min(deg - j, 32);
        long long my = 0;
        if (lane < cnt) {
            int2 se = __ldg(&g_epack[off + j + lane]);
            my = ((long long)se.y << 32) | (unsigned int)se.x;
        }
        int jj = 0;
        int u4 = cnt & ~3;
        for (; jj < u4; jj += 4) {
            float4 hs[4], eg[4]; float p[4];
            #pragma unroll
            for (int u = 0; u < 4; u++) {
                long long pk = __shfl_sync(0xffffffffu, my, jj + u);
                int s = (int)(unsigned int)pk;
                int e = (int)(pk >> 32);
                hs[u] = *(const float4*)&g_h[(size_t)s * DD + lane * 4];
                eg[u] = *(const float4*)&g_eg4f[(size_t)e * 4];
                p[u] = hs[u].x*hd.x + hs[u].y*hd.y + hs[u].z*hd.z + hs[u].w*hd.w;
            }
            #pragma unroll
            for (int o = 16; o; o >>= 1) {
                #pragma unroll
                for (int u = 0; u < 4; u++) p[u] += __shfl_xor_sync(0xffffffffu, p[u], o);
            }
            #pragma unroll
            for (int u = 0; u < 4; u++) {
                float ea = __expf(p[u]);
                za += ea; z0 += eg[u].x; z1 += eg[u].y; z2 += eg[u].z;
                aP.x += ea*hs[u].x; aP.y += ea*hs[u].y; aP.z += ea*hs[u].z; aP.w += ea*hs[u].w;
                q0.x += eg[u].x*hs[u].x; q0.y += eg[u].x*hs[u].y; q0.z += eg[u].x*hs[u].z; q0.w += eg[u].x*hs[u].w;
                q1.x += eg[u].y*hs[u].x; q1.y += eg[u].y*hs[u].y; q1.z += eg[u].y*hs[u].z; q1.w += eg[u].y*hs[u].w;
                q2.x += eg[u].z*hs[u].x; q2.y += eg[u].z*hs[u].y; q2.z += eg[u].z*hs[u].z; q2.w += eg[u].z*hs[u].w;
            }
        }
        for (; jj < cnt; jj++) {
            long long pk = __shfl_sync(0xffffffffu, my, jj);
            int s = (int)(unsigned int)pk;
            int e = (int)(pk >> 32);
            float4 hs = *(const float4*)&g_h[(size_t)s * DD + lane * 4];
            float4 eg = *(const float4*)&g_eg4f[(size_t)e * 4];
            float pa = hs.x*hd.x + hs.y*hd.y + hs.z*hd.z + hs.w*hd.w;
            #pragma unroll
            for (int o = 16; o; o >>= 1) pa += __shfl_xor_sync(0xffffffffu, pa, o);
            float ea = __expf(pa);
            za += ea; z0 += eg.x; z1 += eg.y; z2 += eg.z;
            aP.x += ea*hs.x; aP.y += ea*hs.y; aP.z += ea*hs.z; aP.w += ea*hs.w;
            q0.x += eg.x*hs.x; q0.y += eg.x*hs.y; q0.z += eg.x*hs.z; q0.w += eg.x*hs.w;
            q1.x += eg.y*hs.x; q1.y += eg.y*hs.y; q1.z += eg.y*hs.z; q1.w += eg.y*hs.w;
            q2.x += eg.z*hs.x; q2.y += eg.z*hs.y; q2.z += eg.z*hs.z; q2.w += eg.z*hs.w;
        }
        j += cnt;
    }

    float sP = 0.f, s0 = 0.f, s1 = 0.f, s2 = 0.f;
    if (deg > 0) {
        sP = 1.f / (3.f * za); s0 = 1.f / (3.f * z0);
        s1 = 1.f / (3.f * z1); s2 = 1.f / (3.f * z2);
    }
    float* base = g_acc + (size_t)n * 512;
    *(float4*)(base + lane * 4)       = make_float4(aP.x*sP, aP.y*sP, aP.z*sP, aP.w*sP);
    *(float4*)(base + 128 + lane * 4) = make_float4(q0.x*s0, q0.y*s0, q0.z*s0, q0.w*s0);
    *(float4*)(base + 256 + lane * 4) = make_float4(q1.x*s1, q1.y*s1, q1.z*s1, q1.w*s1);
    *(float4*)(base + 384 + lane * 4) = make_float4(q2.x*s2, q2.y*s2, q2.z*s2, q2.w*s2);
    if (lane == 0) g_za[n] = (deg > 0) ? za : 0.f;
}

// ---------------- kernel D: finalize per node (tf32 mma, 128 nodes/CTA) ----------------
#define FW_STRIDE 132
#define SMEM_FIN  ((16896 * 2) * 4)

__global__ void __launch_bounds__(256, 1) k_final(const float* __restrict__ nf,
                                                  const float* __restrict__ outb,
                                                  const float* __restrict__ gW,
                                                  const float* __restrict__ gb,
                                                  float* __restrict__ out)
{
    extern __shared__ float sm[];
    float* WsT = sm;
    float* As  = sm + 16896;

    int tid = threadIdx.x;
    int w = tid >> 5, lane = tid & 31;
    int g = lane >> 2, tig = lane & 3;
    int nbase = blockIdx.x * NB;

    float c[16][4];
    #pragma unroll
    for (int i = 0; i < 16; i++) { c[i][0]=0.f; c[i][1]=0.f; c[i][2]=0.f; c[i][3]=0.f; }

    for (int ph = 0; ph < 4; ph++) {
        __syncthreads();   // prior mma done reading As/WsT
        // stage As (128 nodes) raw via cp.async; zero-fill OOB
        for (int q = tid; q < 4096; q += 256) {
            int nn = q >> 5, kq = q & 31;
            int gn = nbase + nn;
            if (gn < NN) cp16(&As[nn * FW_STRIDE + kq * 4],
                              &g_acc[(size_t)gn * 512 + ph * 128 + kq * 4]);
            else *(float4*)&As[nn * FW_STRIDE + kq * 4] = make_float4(0.f,0.f,0.f,0.f);
        }
        #pragma unroll
        for (int pass = 0; pass < 2; pass++) {
            const float* Csrc = (pass ? g_Ct_lo : g_Ct_hi) + ph * 16384;
            for (int q = tid; q < 4096; q += 256) {
                int rr = q >> 5, kq = q & 31;
                cp16(&WsT[rr * FW_STRIDE + kq * 4], &Csrc[rr * 128 + kq * 4]);
            }
            CP_COMMIT; CP_WAIT0;
            __syncthreads();
            uint32_t a0[16], a1[16], a2[16], a3[16];
            const float* w0 = &WsT[(w * 16 + g) * FW_STRIDE];
            const float* w1 = &WsT[(w * 16 + 8 + g) * FW_STRIDE];
            #pragma unroll
            for (int kk = 0; kk < 16; kk++) {
                a0[kk] = __float_as_uint(w0[kk * 8 + tig]);
                a2[kk] = __float_as_uint(w0[kk * 8 + tig + 4]);
                a1[kk] = __float_as_uint(w1[kk * 8 + tig]);
                a3[kk] = __float_as_uint(w1[kk * 8 + tig + 4]);
            }
            #pragma unroll
            for (int nt = 0; nt < 16; nt++) {
                const float* bp = &As[(nt * 8 + g) * FW_STRIDE];
                #pragma unroll
                for (int kk = 0; kk < 16; kk++) {
                    uint32_t b0 = __float_as_uint(bp[kk * 8 + tig]);
                    uint32_t b1 = __float_as_uint(bp[kk * 8 + tig + 4]);
                    mma_tf32(c[nt][0], c[nt][1], c[nt][2], c[nt][3],
                             a0[kk], a1[kk], a2[kk], a3[kk], b0, b1);
                }
            }
            if (pass == 0) __syncthreads();   // before overwriting WsT with lo
        }
    }

    __syncthreads();
    #pragma unroll
    for (int nt = 0; nt < 16; nt++) {
        int n0 = nt * 8 + tig * 2;
        As[n0 * FW_STRIDE + w * 16 + g]           = c[nt][0];
        As[(n0 + 1) * FW_STRIDE + w * 16 + g]     = c[nt][1];
        As[n0 * FW_STRIDE + w * 16 + 8 + g]       = c[nt][2];
        As[(n0 + 1) * FW_STRIDE + w * 16 + 8 + g] = c[nt][3];
    }
    __syncthreads();

    float4 b4  = *(const float4*)&outb[lane * 4];
    float4 gw4 = *(const float4*)&gW[lane * 4];
    float gb0 = __ldg(gb);
    #pragma unroll
    for (int t = 0; t < 16; t++) {
        int i = w * 16 + t;
        int n = nbase + i;
        if (n >= NN) break;
        float4 vv = *(const float4*)&As[i * FW_STRIDE + lane * 4];
        bool ok = (g_za[n] > 0.f);
        float4 pre = make_float4(fmaxf(vv.x + b4.x, 0.f), fmaxf(vv.y + b4.y, 0.f),
                                 fmaxf(vv.z + b4.z, 0.f), fmaxf(vv.w + b4.w, 0.f));
        float4 hv  = *(const float4*)&g_h[(size_t)n * DD + lane * 4];
        float4 ho  = ok ? pre : hv;
        float4 nfv = *(const float4*)&nf[(size_t)n * DD + lane * 4];
        float gp = nfv.x * gw4.x + nfv.y * gw4.y + nfv.z * gw4.z + nfv.w * gw4.w;
        #pragma unroll
        for (int o = 16; o; o >>= 1) gp += __shfl_xor_sync(0xffffffffu, gp, o);
        float gate = sigmoidf_(gp + gb0);
        float4 oo = make_float4(gate * ho.x + (1.f - gate) * nfv.x,
                                gate * ho.y + (1.f - gate) * nfv.y,
                                gate * ho.z + (1.f - gate) * nfv.z,
                                gate * ho.w + (1.f - gate) * nfv.w);
        *(float4*)&out[(size_t)n * DD + lane * 4] = oo;
    }
}

// ---------------- launcher ----------------
extern "C" void kernel_launch(void* const* d_in, const int* in_sizes, int n_in,
                              void* d_out, int out_size)
{
    const float* nf   = (const float*)d_in[0];
    const float* ef   = (const float*)d_in[1];
    const int*   src  = (const int*)  d_in[2];
    const int*   dst  = (const int*)  d_in[3];
    const float* natt = (const float*)d_in[4];
    const float* relW = (const float*)d_in[5];
    const float* W1   = (const float*)d_in[6];
    const float* b1   = (const float*)d_in[7];
    const float* W2   = (const float*)d_in[8];
    const float* b2   = (const float*)d_in[9];
    const float* nfcW = (const float*)d_in[10];
    const float* nfcb = (const float*)d_in[11];
    const float* efcW = (const float*)d_in[12];
    const float* efcb = (const float*)d_in[13];
    const float* outW = (const float*)d_in[14];
    const float* outb = (const float*)d_in[15];
    const float* gW   = (const float*)d_in[16];
    const float* gb   = (const float*)d_in[17];
    float* out = (float*)d_out;

    static cudaStream_t s_side = nullptr;
    static cudaEvent_t e_fork = nullptr, e_prepF = nullptr, e_fill = nullptr, e_comb = nullptr;
    if (s_side == nullptr) {
        cudaStreamCreateWithFlags(&s_side, cudaStreamNonBlocking);
        cudaEventCreateWithFlags(&e_fork,  cudaEventDisableTiming);
        cudaEventCreateWithFlags(&e_prepF, cudaEventDisableTiming);
        cudaEventCreateWithFlags(&e_fill,  cudaEventDisableTiming);
        cudaEventCreateWithFlags(&e_comb,  cudaEventDisableTiming);
    }

    void* pDeg;
    cudaGetSymbolAddress(&pDeg, g_deg);

    cudaFuncSetAttribute(k_node_fc, cudaFuncAttributeMaxDynamicSharedMemorySize, SMEM_NFC);
    cudaFuncSetAttribute(k_mlp,     cudaFuncAttributeMaxDynamicSharedMemorySize, SMEM_MLP);
    cudaFuncSetAttribute(k_final,   cudaFuncAttributeMaxDynamicSharedMemorySize, SMEM_FIN);

    // fork: prepF + CSR build + combine on side stream
    cudaEventRecord(e_fork, 0);
    cudaStreamWaitEvent(s_side, e_fork, 0);
    k_prepF<<<192, 128, 0, s_side>>>(efcW, efcb, W1, b1);
    cudaEventRecord(e_prepF, s_side);
    cudaMemsetAsync(pDeg, 0, NN * sizeof(int), s_side);
    k_hist<<<(EE + 255) / 256, 256, 0, s_side>>>(dst);
    k_scan<<<1, 1024, 0, s_side>>>();
    k_fill<<<(EE + 255) / 256, 256, 0, s_side>>>(src, dst);
    cudaEventRecord(e_fill, s_side);
    k_combine<<<512, 128, 0, s_side>>>(natt, relW, outW);
    cudaEventRecord(e_comb, s_side);

    // main chain
    k_prepW<<<128, 128>>>(nfcW);
    k_node_fc<<<(NN + 127) / 128, 256, SMEM_NFC>>>(nf, nfcb);
    cudaStreamWaitEvent(0, e_prepF, 0);
    k_mlp<<<GRID_MLP, 768, SMEM_MLP>>>(ef, W2, b2);

    // join: gather needs CSR + mlp + h; final needs combine
    cudaStreamWaitEvent(0, e_fill, 0);
    k_gather<<<(NN + 7) / 8, 256>>>();
    cudaStreamWaitEvent(0, e_comb, 0);
    k_final<<<(NN + NB - 1) / NB, 256, SMEM_FIN>>>(nf, outb, gW, gb, out);
}

// round 13
// speedup vs baseline: 1.0171x; 1.0171x over previous
#include <cuda_runtime.h>
#include <cuda_bf16.h>
#include <math.h>
#include <stdint.h>

#define NN   20000
#define NNP  20032
#define EE   320000
#define DD   128
#define DEH  64
#define NTILES (EE / 128)   // 2500
#define GRID_MLP 148
#define NB   64             // nodes per k_final CTA (2 CTA/SM — wave-balanced)

// ---------------- scratch (device globals; no allocation allowed) ----------------
__device__ float g_h[NN * DD];                 // node_fc output h
__device__ float g_acc[(size_t)NNP * 512];     // per-node [P | Q0 | Q1 | Q2] (pre-scaled)
__device__ float g_za[NNP];                    // sum exp(a) per dst (mask)
__device__ float g_Ct_hi[4 * DD * DD];         // folded C, transposed [ph][out][k], tf32 hi
__device__ float g_Ct_lo[4 * DD * DD];         // tf32 lo residual
__device__ float g_Wt_hi[DD * DD];             // node_fc W transposed [out][k], tf32 hi
__device__ float g_Wt_lo[DD * DD];             // tf32 lo residual
__device__ float g_eg4f[(size_t)EE * 4];       // [e] = {eg0, eg1, eg2, -}
__device__ float g_B[384 * 64];                // folded MLP weights Gᵀ (tf32-rounded fp32)
__device__ float g_bb[384];                    // folded bias bb1
__device__ int   g_deg[NN];
__device__ int   g_off[NN];
__device__ int   g_cur[NN];
__device__ int2  g_epack[EE];                  // (src, e) sorted by dst

__device__ __forceinline__ float sigmoidf_(float x) { return 1.f / (1.f + __expf(-x)); }

__device__ __forceinline__ uint32_t smem_to_u32(const void* p) {
    uint32_t a;
    asm("{ .reg .u64 t; cvta.to.shared.u64 t, %1; cvt.u32.u64 %0, t; }" : "=r"(a) : "l"(p));
    return a;
}
__device__ __forceinline__ uint32_t tf32_rna(float x) {
    uint32_t r; asm("cvt.rna.tf32.f32 %0, %1;" : "=r"(r) : "f"(x)); return r;
}
__device__ __forceinline__ float tf32f(float x) { return __uint_as_float(tf32_rna(x)); }
__device__ __forceinline__ void mma_tf32(float& c0, float& c1, float& c2, float& c3,
                                         uint32_t a0, uint32_t a1, uint32_t a2, uint32_t a3,
                                         uint32_t b0, uint32_t b1) {
    asm volatile("mma.sync.aligned.m16n8k8.row.col.f32.tf32.tf32.f32 "
                 "{%0,%1,%2,%3}, {%4,%5,%6,%7}, {%8,%9}, {%0,%1,%2,%3};"
                 : "+f"(c0), "+f"(c1), "+f"(c2), "+f"(c3)
                 : "r"(a0), "r"(a1), "r"(a2), "r"(a3), "r"(b0), "r"(b1));
}
__device__ __forceinline__ void cp16(float* dst_smem, const float* src) {
    uint32_t d = smem_to_u32(dst_smem);
    asm volatile("cp.async.ca.shared.global [%0], [%1], 16;" :: "r"(d), "l"(src));
}
#define CP_COMMIT asm volatile("cp.async.commit_group;" ::: "memory")
#define CP_WAIT2  asm volatile("cp.async.wait_group 2;"  ::: "memory")
#define CP_WAIT0  asm volatile("cp.async.wait_group 0;"  ::: "memory")

// ---------------- prepW (critical path, tiny): node_fc weight transpose + split ----------------
__global__ void __launch_bounds__(128) k_prepW(const float* __restrict__ nfcW)
{
    int k = blockIdx.x, c = threadIdx.x;
    float v = nfcW[k * DD + c];
    float hi = tf32f(v);
    g_Wt_hi[c * DD + k] = hi;
    g_Wt_lo[c * DD + k] = tf32f(v - hi);
}

// ---------------- prepF (side stream): fold G = efcW @ W1 (tf32) + bias ----------------
__global__ void __launch_bounds__(128) k_prepF(const float* __restrict__ efcW,
                                               const float* __restrict__ efcb,
                                               const float* __restrict__ W1,
                                               const float* __restrict__ b1)
{
    __shared__ float sW[4096];   // transposed efcW: sW[fp*64 + k]
    int tid = threadIdx.x;
    for (int i = tid; i < 4096; i += 128) {
        int k = i >> 6, fp = i & 63;
        sW[fp * 64 + k] = efcW[i];
    }
    __syncthreads();
    int half = tid >> 6;
    int k = tid & 63;
    int n = blockIdx.x * 2 + half;
    int m = n >> 7, f = n & 127;
    float acc = 0.f;
    float bacc = b1[n];
    #pragma unroll 4
    for (int fp = 0; fp < DEH; fp++) {
        float w1v = __ldg(&W1[(m * DEH + fp) * DD + f]);
        acc += sW[fp * 64 + k] * w1v;
        bacc += __ldg(&efcb[fp]) * w1v;
    }
    g_B[n * 64 + k] = tf32f(acc);
    if (k == 0) g_bb[n] = bacc;
}

// ---------------- combine (side stream): C0 = Wsum@U_top, Cm = W_m@U_bot ----------------
__global__ void __launch_bounds__(128) k_combine(const float* __restrict__ natt,
                                                 const float* __restrict__ relW,
                                                 const float* __restrict__ outW)
{
    __shared__ float row[DD];
    int i = blockIdx.x >> 7;          // phase 0..3
    int d = blockIdx.x & 127;         // k
    int c = threadIdx.x;              // output
    if (i == 0)
        row[c] = natt[d * DD + c] + natt[DD * DD + d * DD + c] + natt[2 * DD * DD + d * DD + c];
    else
        row[c] = relW[(i - 1) * DD * DD + d * DD + c];
    __syncthreads();
    const float* U = (i == 0) ? outW : outW + DD * DD;
    float acc = 0.f;
    #pragma unroll 8
    for (int f = 0; f < DD; f++) acc += row[f] * U[f * DD + c];
    float hi = tf32f(acc);
    g_Ct_hi[i * DD * DD + c * DD + d] = hi;
    g_Ct_lo[i * DD * DD + c * DD + d] = tf32f(acc - hi);
}

// ---------------- kernel A: h = nf @ node_fc_W + b  (tf32 mma, 3-pass compensated) ----------------
#define NF_STRIDE 132
#define SMEM_NFC ((16896 * 2 + 128) * 4)

__global__ void __launch_bounds__(256, 1) k_node_fc(const float* __restrict__ nf,
                                                    const float* __restrict__ b)
{
    extern __shared__ float sm[];
    float* Ws  = sm;
    float* As  = sm + 16896;
    float* bsm = sm + 2 * 16896;

    int tid = threadIdx.x;
    int w = tid >> 5, lane = tid & 31;
    int g = lane >> 2, tig = lane & 3;
    int nbase = blockIdx.x * 128;
    if (tid < 128) bsm[tid] = b[tid];

    float c[16][4];
    #pragma unroll
    for (int i = 0; i < 16; i++) { c[i][0]=0.f; c[i][1]=0.f; c[i][2]=0.f; c[i][3]=0.f; }

    #pragma unroll
    for (int pass = 0; pass < 3; pass++) {
        __syncthreads();
        if (pass != 1) {
            bool lo = (pass == 2);
            for (int q = tid; q < 4096; q += 256) {
                int n = q >> 5, kq = q & 31;
                int gn = nbase + n;
                float4 v = make_float4(0.f,0.f,0.f,0.f);
                if (gn < NN) v = *(const float4*)&nf[(size_t)gn * DD + kq * 4];
                float4 o;
                if (!lo) o = make_float4(tf32f(v.x), tf32f(v.y), tf32f(v.z), tf32f(v.w));
                else     o = make_float4(tf32f(v.x - tf32f(v.x)), tf32f(v.y - tf32f(v.y)),
                                         tf32f(v.z - tf32f(v.z)), tf32f(v.w - tf32f(v.w)));
                *(float4*)&As[n * NF_STRIDE + kq * 4] = o;
            }
        }
        const float* Wsrc = (pass == 1) ? g_Wt_lo : g_Wt_hi;
        for (int q = tid; q < 4096; q += 256) {
            int rr = q >> 5, kq = q & 31;
            cp16(&Ws[rr * NF_STRIDE + kq * 4], &Wsrc[rr * DD + kq * 4]);
        }
        CP_COMMIT; CP_WAIT0;
        __syncthreads();

        uint32_t a0[16], a1[16], a2[16], a3[16];
        const float* w0 = &Ws[(w * 16 + g) * NF_STRIDE];
        const float* w1 = &Ws[(w * 16 + 8 + g) * NF_STRIDE];
        #pragma unroll
        for (int kk = 0; kk < 16; kk++) {
            a0[kk] = __float_as_uint(w0[kk * 8 + tig]);
            a2[kk] = __float_as_uint(w0[kk * 8 + tig + 4]);
            a1[kk] = __float_as_uint(w1[kk * 8 + tig]);
            a3[kk] = __float_as_uint(w1[kk * 8 + tig + 4]);
        }
        #pragma unroll
        for (int nt = 0; nt < 16; nt++) {
            const float* bp = &As[(nt * 8 + g) * NF_STRIDE];
            #pragma unroll
            for (int kk = 0; kk < 16; kk++) {
                uint32_t b0 = __float_as_uint(bp[kk * 8 + tig]);
                uint32_t b1 = __float_as_uint(bp[kk * 8 + tig + 4]);
                mma_tf32(c[nt][0], c[nt][1], c[nt][2], c[nt][3],
                         a0[kk], a1[kk], a2[kk], a3[kk], b0, b1);
            }
        }
    }

    __syncthreads();
    #pragma unroll
    for (int nt = 0; nt < 16; nt++) {
        int n0 = nt * 8 + tig * 2;
        As[n0 * NF_STRIDE + w * 16 + g]           = c[nt][0];
        As[(n0 + 1) * NF_STRIDE + w * 16 + g]     = c[nt][1];
        As[n0 * NF_STRIDE + w * 16 + 8 + g]       = c[nt][2];
        As[(n0 + 1) * NF_STRIDE + w * 16 + 8 + g] = c[nt][3];
    }
    __syncthreads();
    for (int q = tid; q < 4096; q += 256) {
        int n = q >> 5, kq = q & 31;
        int gn = nbase + n;
        if (gn < NN) {
            float4 v = *(const float4*)&As[n * NF_STRIDE + kq * 4];
            float4 bb = *(const float4*)&bsm[kq * 4];
            *(float4*)&g_h[(size_t)gn * DD + kq * 4] =
                make_float4(v.x + bb.x, v.y + bb.y, v.z + bb.z, v.w + bb.w);
        }
    }
}

// ---------------- CSR build ----------------
__global__ void k_hist(const int* __restrict__ dst)
{
    int e = blockIdx.x * 256 + threadIdx.x;
    if (e < EE) atomicAdd(&g_deg[dst[e]], 1);
}

__global__ void __launch_bounds__(1024) k_scan()
{
    int tid = threadIdx.x;
    int lane = tid & 31, w = tid >> 5;
    int base = tid * 20;
    int loc[20]; int s = 0;
    #pragma unroll
    for (int j = 0; j < 20; j++) {
        int n = base + j;
        int d = (n < NN) ? g_deg[n] : 0;
        loc[j] = s; s += d;
    }
    int v = s;
    #pragma unroll
    for (int off = 1; off < 32; off <<= 1) {
        int u = __shfl_up_sync(0xffffffffu, v, off);
        if (lane >= off) v += u;
    }
    __shared__ int wsum[32];
    if (lane == 31) wsum[w] = v;
    __syncthreads();
    if (w == 0) {
        int t = wsum[lane];
        #pragma unroll
        for (int off = 1; off < 32; off <<= 1) {
            int u = __shfl_up_sync(0xffffffffu, t, off);
            if (lane >= off) t += u;
        }
        wsum[lane] = t;
    }
    __syncthreads();
    int excl = v - s + (w > 0 ? wsum[w - 1] : 0);
    #pragma unroll
    for (int j = 0; j < 20; j++) {
        int n = base + j;
        if (n < NN) { int o = excl + loc[j]; g_off[n] = o; g_cur[n] = o; }
    }
}

__global__ void k_fill(const int* __restrict__ src, const int* __restrict__ dst)
{
    int e = blockIdx.x * 256 + threadIdx.x;
    if (e < EE) {
        int d = dst[e];
        int pos = atomicAdd(&g_cur[d], 1);
        g_epack[pos] = make_int2(src[e], e);
    }
}

// ---------------- kernel B: tensor-core (mma.sync tf32) edge MLP -> g_eg4f[.xyz] ----------------
// 3-stage cp.async pipeline; B quad-packed so each LDS.128 feeds 2 mmas
#define BP_STRIDE 72
#define A_STRIDE  68
#define A_BUF_F   (128 * A_STRIDE)          // 8704 floats
#define OFF_EPI   27648
#define OFF_A     (27648 + 768)
#define SMEM_MLP  ((27648 + 768 + 3 * A_BUF_F) * 4)

__global__ void __launch_bounds__(768, 1) k_mlp(const float* __restrict__ ef,
                                                const float* __restrict__ W2,
                                                const float* __restrict__ b2)
{
    extern __shared__ float sm[];
    float*  Bp  = sm;
    float2* epi = (float2*)(sm + OFF_EPI);
    float*  As  = sm + OFF_A;

    int tid = threadIdx.x;
    int wid = tid >> 5, lane = tid & 31;
    int g = lane >> 2, tig = lane & 3;
    int m = wid >> 3;          // head 0..2
    int r = wid & 7;           // row slice 0..7
    int rowbase = r * 16;

    // quad-packed B: float4 at [n*72 + (kk>>1)*16 + (t&3)*4] =
    //   {B[n][2p*8+t], B[n][2p*8+t+4], B[n][(2p+1)*8+t], B[n][(2p+1)*8+t+4]}
    for (int i = tid; i < 384 * 64; i += 768) {
        int n = i >> 6, k = i & 63;
        int kk = k >> 3, t = k & 7;
        int pos = n * BP_STRIDE + (kk >> 1) * 16 + (t & 3) * 4 + (kk & 1) * 2 + (t >> 2);
        Bp[pos] = g_B[i];
    }
    if (tid < 384) epi[tid] = make_float2(g_bb[tid], __ldg(W2 + tid));
    __syncthreads();

    float b2m = __ldg(b2 + m);

    int t0 = blockIdx.x;
    // prologue: stages 0 and 1
    #pragma unroll
    for (int p = 0; p < 2; p++) {
        int tp = t0 + p * GRID_MLP;
        if (tp < NTILES) {
            const float* srcb = ef + (size_t)tp * 8192;
            float* dstb = As + p * A_BUF_F;
            for (int c = tid; c < 2048; c += 768)
                cp16(dstb + (c >> 4) * A_STRIDE + (c & 15) * 4, srcb + c * 4);
        }
        CP_COMMIT;
    }

    int buf = 0;
    for (int t = t0; t < NTILES; t += GRID_MLP) {
        int tn = t + 2 * GRID_MLP;
        if (tn < NTILES) {
            const float* srcb = ef + (size_t)tn * 8192;
            int slot = buf + 2; if (slot >= 3) slot -= 3;
            float* dstb = As + slot * A_BUF_F;
            for (int c = tid; c < 2048; c += 768)
                cp16(dstb + (c >> 4) * A_STRIDE + (c & 15) * 4, srcb + c * 4);
        }
        CP_COMMIT;
        CP_WAIT2;              // oldest group (current buf) complete
        __syncthreads();

        const float* A = As + buf * A_BUF_F;
        const float* r0p = A + (rowbase + g) * A_STRIDE;
        const float* r1p = A + (rowbase + g + 8) * A_STRIDE;
        uint32_t a0[8], a1[8], a2[8], a3[8];
        #pragma unroll
        for (int kk = 0; kk < 8; kk++) {
            a0[kk] = __float_as_uint(r0p[kk * 8 + tig]);
            a2[kk] = __float_as_uint(r0p[kk * 8 + tig + 4]);
            a1[kk] = __float_as_uint(r1p[kk * 8 + tig]);
            a3[kk] = __float_as_uint(r1p[kk * 8 + tig + 4]);
        }

        float p0 = 0.f, p1 = 0.f;
        #pragma unroll 4
        for (int nt = 0; nt < 16; nt++) {
            int n0 = m * 128 + nt * 8;
            float c0 = 0.f, c1 = 0.f, c2 = 0.f, c3 = 0.f;
            const float4* bp4 = (const float4*)(Bp + (n0 + g) * BP_STRIDE) + tig;
            #pragma unroll
            for (int kkp = 0; kkp < 4; kkp++) {
                float4 bv = bp4[kkp * 4];
                int ke = 2 * kkp, ko = 2 * kkp + 1;
                mma_tf32(c0, c1, c2, c3, a0[ke], a1[ke], a2[ke], a3[ke],
                         __float_as_uint(bv.x), __float_as_uint(bv.y));
                mma_tf32(c0, c1, c2, c3, a0[ko], a1[ko], a2[ko], a3[ko],
                         __float_as_uint(bv.z), __float_as_uint(bv.w));
            }
            float2 e0 = epi[n0 + 2 * tig];
            float2 e1 = epi[n0 + 2 * tig + 1];
            p0 += fmaxf(c0 + e0.x, 0.f) * e0.y + fmaxf(c1 + e1.x, 0.f) * e1.y;
            p1 += fmaxf(c2 + e0.x, 0.f) * e0.y + fmaxf(c3 + e1.x, 0.f) * e1.y;
        }
        #pragma unroll
        for (int off = 1; off <= 2; off <<= 1) {
            p0 += __shfl_xor_sync(0xffffffffu, p0, off);
            p1 += __shfl_xor_sync(0xffffffffu, p1, off);
        }
        if (tig == 0) {
            int e = t * 128 + rowbase + g;
            g_eg4f[(size_t)(e)     * 4 + m] = __expf(sigmoidf_(p0 + b2m));
            g_eg4f[(size_t)(e + 8) * 4 + m] = __expf(sigmoidf_(p1 + b2m));
        }
        __syncthreads();
        buf++; if (buf >= 3) buf = 0;
    }
}

// ---------------- kernel C: gather (warp per dst node; batched epack via shfl) ----------------
__global__ void __launch_bounds__(256) k_gather()
{
    int n = (blockIdx.x * 256 + threadIdx.x) >> 5;
    int lane = threadIdx.x & 31;
    if (n >= NN) return;

    int off = g_off[n];
    int deg = g_deg[n];
    float4 hd = *(const float4*)&g_h[(size_t)n * DD + lane * 4];

    float4 aP = make_float4(0.f,0.f,0.f,0.f), q0 = aP, q1 = aP, q2 = aP;
    float za = 0.f, z0 = 0.f, z1 = 0.f, z2 = 0.f;

    int j = 0;
    while (j < deg) {
        int cnt = min(deg - j, 32);
        long long my = 0;
        if (lane < cnt) {
            int2 se = __ldg(&g_epack[off + j + lane]);
            my = ((long long)se.y << 32) | (unsigned int)se.x;
        }
        int jj = 0;
        int u4 = cnt & ~3;
        for (; jj < u4; jj += 4) {
            float4 hs[4], eg[4]; float p[4];
            #pragma unroll
            for (int u = 0; u < 4; u++) {
                long long pk = __shfl_sync(0xffffffffu, my, jj + u);
                int s = (int)(unsigned int)pk;
                int e = (int)(pk >> 32);
                hs[u] = *(const float4*)&g_h[(size_t)s * DD + lane * 4];
                eg[u] = *(const float4*)&g_eg4f[(size_t)e * 4];
                p[u] = hs[u].x*hd.x + hs[u].y*hd.y + hs[u].z*hd.z + hs[u].w*hd.w;
            }
            #pragma unroll
            for (int o = 16; o; o >>= 1) {
                #pragma unroll
                for (int u = 0; u < 4; u++) p[u] += __shfl_xor_sync(0xffffffffu, p[u], o);
            }
            #pragma unroll
            for (int u = 0; u < 4; u++) {
                float ea = __expf(p[u]);
                za += ea; z0 += eg[u].x; z1 += eg[u].y; z2 += eg[u].z;
                aP.x += ea*hs[u].x; aP.y += ea*hs[u].y; aP.z += ea*hs[u].z; aP.w += ea*hs[u].w;
                q0.x += eg[u].x*hs[u].x; q0.y += eg[u].x*hs[u].y; q0.z += eg[u].x*hs[u].z; q0.w += eg[u].x*hs[u].w;
                q1.x += eg[u].y*hs[u].x; q1.y += eg[u].y*hs[u].y; q1.z += eg[u].y*hs[u].z; q1.w += eg[u].y*hs[u].w;
                q2.x += eg[u].z*hs[u].x; q2.y += eg[u].z*hs[u].y; q2.z += eg[u].z*hs[u].z; q2.w += eg[u].z*hs[u].w;
            }
        }
        for (; jj < cnt; jj++) {
            long long pk = __shfl_sync(0xffffffffu, my, jj);
            int s = (int)(unsigned int)pk;
            int e = (int)(pk >> 32);
            float4 hs = *(const float4*)&g_h[(size_t)s * DD + lane * 4];
            float4 eg = *(const float4*)&g_eg4f[(size_t)e * 4];
            float pa = hs.x*hd.x + hs.y*hd.y + hs.z*hd.z + hs.w*hd.w;
            #pragma unroll
            for (int o = 16; o; o >>= 1) pa += __shfl_xor_sync(0xffffffffu, pa, o);
            float ea = __expf(pa);
            za += ea; z0 += eg.x; z1 += eg.y; z2 += eg.z;
            aP.x += ea*hs.x; aP.y += ea*hs.y; aP.z += ea*hs.z; aP.w += ea*hs.w;
            q0.x += eg.x*hs.x; q0.y += eg.x*hs.y; q0.z += eg.x*hs.z; q0.w += eg.x*hs.w;
            q1.x += eg.y*hs.x; q1.y += eg.y*hs.y; q1.z += eg.y*hs.z; q1.w += eg.y*hs.w;
            q2.x += eg.z*hs.x; q2.y += eg.z*hs.y; q2.z += eg.z*hs.z; q2.w += eg.z*hs.w;
        }
        j += cnt;
    }

    float sP = 0.f, s0 = 0.f, s1 = 0.f, s2 = 0.f;
    if (deg > 0) {
        sP = 1.f / (3.f * za); s0 = 1.f / (3.f * z0);
        s1 = 1.f / (3.f * z1); s2 = 1.f / (3.f * z2);
    }
    float* base = g_acc + (size_t)n * 512;
    *(float4*)(base + lane * 4)       = make_float4(aP.x*sP, aP.y*sP, aP.z*sP, aP.w*sP);
    *(float4*)(base + 128 + lane * 4) = make_float4(q0.x*s0, q0.y*s0, q0.z*s0, q0.w*s0);
    *(float4*)(base + 256 + lane * 4) = make_float4(q1.x*s1, q1.y*s1, q1.z*s1, q1.w*s1);
    *(float4*)(base + 384 + lane * 4) = make_float4(q2.x*s2, q2.y*s2, q2.z*s2, q2.w*s2);
    if (lane == 0) g_za[n] = (deg > 0) ? za : 0.f;
}

// ---------------- kernel D: finalize per node (tf32 mma, NB=64, 2 CTA/SM) ----------------
#define FW_STRIDE 132
#define SMEM_FIN  ((16896 + 8448) * 4)

__global__ void __launch_bounds__(256, 2) k_final(const float* __restrict__ nf,
                                                  const float* __restrict__ outb,
                                                  const float* __restrict__ gW,
                                                  const float* __restrict__ gb,
                                                  float* __restrict__ out)
{
    extern __shared__ float sm[];
    float* WsT = sm;
    float* As  = sm + 16896;

    int tid = threadIdx.x;
    int w = tid >> 5, lane = tid & 31;
    int g = lane >> 2, tig = lane & 3;
    int nbase = blockIdx.x * NB;

    float c[8][4];
    #pragma unroll
    for (int i = 0; i < 8; i++) { c[i][0]=0.f; c[i][1]=0.f; c[i][2]=0.f; c[i][3]=0.f; }

    for (int ph = 0; ph < 4; ph++) {
        __syncthreads();   // prior mma done reading As/WsT
        // stage As raw via cp.async (HW truncates to tf32); zero-fill OOB
        for (int q = tid; q < 2048; q += 256) {
            int nn = q >> 5, kq = q & 31;
            int gn = nbase + nn;
            if (gn < NN) cp16(&As[nn * FW_STRIDE + kq * 4],
                              &g_acc[(size_t)gn * 512 + ph * 128 + kq * 4]);
            else *(float4*)&As[nn * FW_STRIDE + kq * 4] = make_float4(0.f,0.f,0.f,0.f);
        }
        #pragma unroll
        for (int pass = 0; pass < 2; pass++) {
            const float* Csrc = (pass ? g_Ct_lo : g_Ct_hi) + ph * 16384;
            for (int q = tid; q < 4096; q += 256) {
                int rr = q >> 5, kq = q & 31;
                cp16(&WsT[rr * FW_STRIDE + kq * 4], &Csrc[rr * 128 + kq * 4]);
            }
            CP_COMMIT; CP_WAIT0;
            __syncthreads();
            uint32_t a0[16], a1[16], a2[16], a3[16];
            const float* w0 = &WsT[(w * 16 + g) * FW_STRIDE];
            const float* w1 = &WsT[(w * 16 + 8 + g) * FW_STRIDE];
            #pragma unroll
            for (int kk = 0; kk < 16; kk++) {
                a0[kk] = __float_as_uint(w0[kk * 8 + tig]);
                a2[kk] = __float_as_uint(w0[kk * 8 + tig + 4]);
                a1[kk] = __float_as_uint(w1[kk * 8 + tig]);
                a3[kk] = __float_as_uint(w1[kk * 8 + tig + 4]);
            }
            #pragma unroll
            for (int nt = 0; nt < 8; nt++) {
                const float* bp = &As[(nt * 8 + g) * FW_STRIDE];
                #pragma unroll
                for (int kk = 0; kk < 16; kk++) {
                    uint32_t b0 = __float_as_uint(bp[kk * 8 + tig]);
                    uint32_t b1 = __float_as_uint(bp[kk * 8 + tig + 4]);
                    mma_tf32(c[nt][0], c[nt][1], c[nt][2], c[nt][3],
                             a0[kk], a1[kk], a2[kk], a3[kk], b0, b1);
                }
            }
            if (pass == 0) __syncthreads();   // before overwriting WsT with lo
        }
    }

    __syncthreads();
    #pragma unroll
    for (int nt = 0; nt < 8; nt++) {
        int n0 = nt * 8 + tig * 2;
        As[n0 * FW_STRIDE + w * 16 + g]           = c[nt][0];
        As[(n0 + 1) * FW_STRIDE + w * 16 + g]     = c[nt][1];
        As[n0 * FW_STRIDE + w * 16 + 8 + g]       = c[nt][2];
        As[(n0 + 1) * FW_STRIDE + w * 16 + 8 + g] = c[nt][3];
    }
    __syncthreads();

    float4 b4  = *(const float4*)&outb[lane * 4];
    float4 gw4 = *(const float4*)&gW[lane * 4];
    float gb0 = __ldg(gb);
    #pragma unroll
    for (int t = 0; t < 8; t++) {
        int i = w * 8 + t;
        int n = nbase + i;
        if (n >= NN) break;
        float4 vv = *(const float4*)&As[i * FW_STRIDE + lane * 4];
        bool ok = (g_za[n] > 0.f);
        float4 pre = make_float4(fmaxf(vv.x + b4.x, 0.f), fmaxf(vv.y + b4.y, 0.f),
                                 fmaxf(vv.z + b4.z, 0.f), fmaxf(vv.w + b4.w, 0.f));
        float4 hv  = *(const float4*)&g_h[(size_t)n * DD + lane * 4];
        float4 ho  = ok ? pre : hv;
        float4 nfv = *(const float4*)&nf[(size_t)n * DD + lane * 4];
        float gp = nfv.x * gw4.x + nfv.y * gw4.y + nfv.z * gw4.z + nfv.w * gw4.w;
        #pragma unroll
        for (int o = 16; o; o >>= 1) gp += __shfl_xor_sync(0xffffffffu, gp, o);
        float gate = sigmoidf_(gp + gb0);
        float4 oo = make_float4(gate * ho.x + (1.f - gate) * nfv.x,
                                gate * ho.y + (1.f - gate) * nfv.y,
                                gate * ho.z + (1.f - gate) * nfv.z,
                                gate * ho.w + (1.f - gate) * nfv.w);
        *(float4*)&out[(size_t)n * DD + lane * 4] = oo;
    }
}

// ---------------- launcher ----------------
extern "C" void kernel_launch(void* const* d_in, const int* in_sizes, int n_in,
                              void* d_out, int out_size)
{
    const float* nf   = (const float*)d_in[0];
    const float* ef   = (const float*)d_in[1];
    const int*   src  = (const int*)  d_in[2];
    const int*   dst  = (const int*)  d_in[3];
    const float* natt = (const float*)d_in[4];
    const float* relW = (const float*)d_in[5];
    const float* W1   = (const float*)d_in[6];
    const float* b1   = (const float*)d_in[7];
    const float* W2   = (const float*)d_in[8];
    const float* b2   = (const float*)d_in[9];
    const float* nfcW = (const float*)d_in[10];
    const float* nfcb = (const float*)d_in[11];
    const float* efcW = (const float*)d_in[12];
    const float* efcb = (const float*)d_in[13];
    const float* outW = (const float*)d_in[14];
    const float* outb = (const float*)d_in[15];
    const float* gW   = (const float*)d_in[16];
    const float* gb   = (const float*)d_in[17];
    float* out = (float*)d_out;

    static cudaStream_t s_side = nullptr;
    static cudaEvent_t e_fork = nullptr, e_prepF = nullptr, e_fill = nullptr, e_comb = nullptr;
    if (s_side == nullptr) {
        cudaStreamCreateWithFlags(&s_side, cudaStreamNonBlocking);
        cudaEventCreateWithFlags(&e_fork,  cudaEventDisableTiming);
        cudaEventCreateWithFlags(&e_prepF, cudaEventDisableTiming);
        cudaEventCreateWithFlags(&e_fill,  cudaEventDisableTiming);
        cudaEventCreateWithFlags(&e_comb,  cudaEventDisableTiming);
    }

    void* pDeg;
    cudaGetSymbolAddress(&pDeg, g_deg);

    cudaFuncSetAttribute(k_node_fc, cudaFuncAttributeMaxDynamicSharedMemorySize, SMEM_NFC);
    cudaFuncSetAttribute(k_mlp,     cudaFuncAttributeMaxDynamicSharedMemorySize, SMEM_MLP);
    cudaFuncSetAttribute(k_final,   cudaFuncAttributeMaxDynamicSharedMemorySize, SMEM_FIN);

    // fork: prepF + CSR build + combine on side stream
    cudaEventRecord(e_fork, 0);
    cudaStreamWaitEvent(s_side, e_fork, 0);
    k_prepF<<<192, 128, 0, s_side>>>(efcW, efcb, W1, b1);
    cudaEventRecord(e_prepF, s_side);
    cudaMemsetAsync(pDeg, 0, NN * sizeof(int), s_side);
    k_hist<<<(EE + 255) / 256, 256, 0, s_side>>>(dst);
    k_scan<<<1, 1024, 0, s_side>>>();
    k_fill<<<(EE + 255) / 256, 256, 0, s_side>>>(src, dst);
    cudaEventRecord(e_fill, s_side);
    k_combine<<<512, 128, 0, s_side>>>(natt, relW, outW);
    cudaEventRecord(e_comb, s_side);

    // main chain
    k_prepW<<<128, 128>>>(nfcW);
    k_node_fc<<<(NN + 127) / 128, 256, SMEM_NFC>>>(nf, nfcb);
    cudaStreamWaitEvent(0, e_prepF, 0);
    k_mlp<<<GRID_MLP, 768, SMEM_MLP>>>(ef, W2, b2);

    // join: gather needs CSR + mlp + h; final needs combine
    cudaStreamWaitEvent(0, e_fill, 0);
    k_gather<<<(NN + 7) / 8, 256>>>();
    cudaStreamWaitEvent(0, e_comb, 0);
    k_final<<<(NN + NB - 1) / NB, 256, SMEM_FIN>>>(nf, outb, gW, gb, out);
}

// round 14
// speedup vs baseline: 1.1874x; 1.1675x over previous
#include <cuda_runtime.h>
#include <cuda_bf16.h>
#include <math.h>
#include <stdint.h>

#define NN   20000
#define NNP  20032
#define EE   320000
#define DD   128
#define DEH  64
#define NTILES (EE / 128)   // 2500
#define GRID_MLP 148
#define NB   64             // nodes per k_final CTA (2 CTA/SM — wave-balanced)

// ---------------- scratch (device globals; no allocation allowed) ----------------
__device__ float g_h[NN * DD];                 // node_fc output h
__device__ float g_acc[(size_t)NNP * 512];     // per-node [P | Q0 | Q1 | Q2] (pre-scaled)
__device__ float g_za[NNP];                    // sum exp(a) per dst (mask)
__device__ float g_Ct_hi[4 * DD * DD];         // folded C, transposed [ph][out][k], tf32 hi
__device__ float g_Ct_lo[4 * DD * DD];         // tf32 lo residual
__device__ float g_Wt_hi[DD * DD];             // node_fc W transposed [out][k], tf32 hi
__device__ float g_Wt_lo[DD * DD];             // tf32 lo residual
__device__ float g_eg4f[(size_t)EE * 4];       // [e] = {eg0, eg1, eg2, -}
__device__ float g_B[384 * 64];                // folded MLP weights Gᵀ (tf32-rounded fp32)
__device__ float g_bb[384];                    // folded bias bb1
__device__ int   g_deg[NN];
__device__ int   g_off[NN];
__device__ int   g_cur[NN];
__device__ int2  g_epack[EE];                  // (src, e) sorted by dst

__device__ __forceinline__ float sigmoidf_(float x) { return 1.f / (1.f + __expf(-x)); }

__device__ __forceinline__ uint32_t smem_to_u32(const void* p) {
    uint32_t a;
    asm("{ .reg .u64 t; cvta.to.shared.u64 t, %1; cvt.u32.u64 %0, t; }" : "=r"(a) : "l"(p));
    return a;
}
__device__ __forceinline__ uint32_t tf32_rna(float x) {
    uint32_t r; asm("cvt.rna.tf32.f32 %0, %1;" : "=r"(r) : "f"(x)); return r;
}
__device__ __forceinline__ float tf32f(float x) { return __uint_as_float(tf32_rna(x)); }
__device__ __forceinline__ void mma_tf32(float& c0, float& c1, float& c2, float& c3,
                                         uint32_t a0, uint32_t a1, uint32_t a2, uint32_t a3,
                                         uint32_t b0, uint32_t b1) {
    asm volatile("mma.sync.aligned.m16n8k8.row.col.f32.tf32.tf32.f32 "
                 "{%0,%1,%2,%3}, {%4,%5,%6,%7}, {%8,%9}, {%0,%1,%2,%3};"
                 : "+f"(c0), "+f"(c1), "+f"(c2), "+f"(c3)
                 : "r"(a0), "r"(a1), "r"(a2), "r"(a3), "r"(b0), "r"(b1));
}
__device__ __forceinline__ void cp16(float* dst_smem, const float* src) {
    uint32_t d = smem_to_u32(dst_smem);
    asm volatile("cp.async.ca.shared.global [%0], [%1], 16;" :: "r"(d), "l"(src));
}
#define CP_COMMIT asm volatile("cp.async.commit_group;" ::: "memory")
#define CP_WAIT2  asm volatile("cp.async.wait_group 2;"  ::: "memory")
#define CP_WAIT0  asm volatile("cp.async.wait_group 0;"  ::: "memory")

// ---------------- prepW (critical path, tiny): node_fc weight transpose + split ----------------
__global__ void __launch_bounds__(128) k_prepW(const float* __restrict__ nfcW)
{
    int k = blockIdx.x, c = threadIdx.x;
    float v = nfcW[k * DD + c];
    float hi = tf32f(v);
    g_Wt_hi[c * DD + k] = hi;
    g_Wt_lo[c * DD + k] = tf32f(v - hi);
}

// ---------------- prepF (side stream): fold G = efcW @ W1 (tf32) + bias ----------------
__global__ void __launch_bounds__(128) k_prepF(const float* __restrict__ efcW,
                                               const float* __restrict__ efcb,
                                               const float* __restrict__ W1,
                                               const float* __restrict__ b1)
{
    __shared__ float sW[4096];   // transposed efcW: sW[fp*64 + k]
    int tid = threadIdx.x;
    for (int i = tid; i < 4096; i += 128) {
        int k = i >> 6, fp = i & 63;
        sW[fp * 64 + k] = efcW[i];
    }
    __syncthreads();
    int half = tid >> 6;
    int k = tid & 63;
    int n = blockIdx.x * 2 + half;
    int m = n >> 7, f = n & 127;
    float acc = 0.f;
    float bacc = b1[n];
    #pragma unroll 4
    for (int fp = 0; fp < DEH; fp++) {
        float w1v = __ldg(&W1[(m * DEH + fp) * DD + f]);
        acc += sW[fp * 64 + k] * w1v;
        bacc += __ldg(&efcb[fp]) * w1v;
    }
    g_B[n * 64 + k] = tf32f(acc);
    if (k == 0) g_bb[n] = bacc;
}

// ---------------- combine (side stream): C0 = Wsum@U_top, Cm = W_m@U_bot ----------------
__global__ void __launch_bounds__(128) k_combine(const float* __restrict__ natt,
                                                 const float* __restrict__ relW,
                                                 const float* __restrict__ outW)
{
    __shared__ float row[DD];
    int i = blockIdx.x >> 7;          // phase 0..3
    int d = blockIdx.x & 127;         // k
    int c = threadIdx.x;              // output
    if (i == 0)
        row[c] = natt[d * DD + c] + natt[DD * DD + d * DD + c] + natt[2 * DD * DD + d * DD + c];
    else
        row[c] = relW[(i - 1) * DD * DD + d * DD + c];
    __syncthreads();
    const float* U = (i == 0) ? outW : outW + DD * DD;
    float acc = 0.f;
    #pragma unroll 8
    for (int f = 0; f < DD; f++) acc += row[f] * U[f * DD + c];
    float hi = tf32f(acc);
    g_Ct_hi[i * DD * DD + c * DD + d] = hi;
    g_Ct_lo[i * DD * DD + c * DD + d] = tf32f(acc - hi);
}

// ---------------- kernel A: h = nf @ node_fc_W + b  (tf32 mma, 3-pass compensated) ----------------
#define NF_STRIDE 132
#define SMEM_NFC ((16896 * 2 + 128) * 4)

__global__ void __launch_bounds__(256, 1) k_node_fc(const float* __restrict__ nf,
                                                    const float* __restrict__ b)
{
    extern __shared__ float sm[];
    float* Ws  = sm;
    float* As  = sm + 16896;
    float* bsm = sm + 2 * 16896;

    int tid = threadIdx.x;
    int w = tid >> 5, lane = tid & 31;
    int g = lane >> 2, tig = lane & 3;
    int nbase = blockIdx.x * 128;
    if (tid < 128) bsm[tid] = b[tid];

    float c[16][4];
    #pragma unroll
    for (int i = 0; i < 16; i++) { c[i][0]=0.f; c[i][1]=0.f; c[i][2]=0.f; c[i][3]=0.f; }

    #pragma unroll
    for (int pass = 0; pass < 3; pass++) {
        __syncthreads();
        if (pass != 1) {
            bool lo = (pass == 2);
            for (int q = tid; q < 4096; q += 256) {
                int n = q >> 5, kq = q & 31;
                int gn = nbase + n;
                float4 v = make_float4(0.f,0.f,0.f,0.f);
                if (gn < NN) v = *(const float4*)&nf[(size_t)gn * DD + kq * 4];
                float4 o;
                if (!lo) o = make_float4(tf32f(v.x), tf32f(v.y), tf32f(v.z), tf32f(v.w));
                else     o = make_float4(tf32f(v.x - tf32f(v.x)), tf32f(v.y - tf32f(v.y)),
                                         tf32f(v.z - tf32f(v.z)), tf32f(v.w - tf32f(v.w)));
                *(float4*)&As[n * NF_STRIDE + kq * 4] = o;
            }
        }
        const float* Wsrc = (pass == 1) ? g_Wt_lo : g_Wt_hi;
        for (int q = tid; q < 4096; q += 256) {
            int rr = q >> 5, kq = q & 31;
            cp16(&Ws[rr * NF_STRIDE + kq * 4], &Wsrc[rr * DD + kq * 4]);
        }
        CP_COMMIT; CP_WAIT0;
        __syncthreads();

        uint32_t a0[16], a1[16], a2[16], a3[16];
        const float* w0 = &Ws[(w * 16 + g) * NF_STRIDE];
        const float* w1 = &Ws[(w * 16 + 8 + g) * NF_STRIDE];
        #pragma unroll
        for (int kk = 0; kk < 16; kk++) {
            a0[kk] = __float_as_uint(w0[kk * 8 + tig]);
            a2[kk] = __float_as_uint(w0[kk * 8 + tig + 4]);
            a1[kk] = __float_as_uint(w1[kk * 8 + tig]);
            a3[kk] = __float_as_uint(w1[kk * 8 + tig + 4]);
        }
        #pragma unroll
        for (int nt = 0; nt < 16; nt++) {
            const float* bp = &As[(nt * 8 + g) * NF_STRIDE];
            #pragma unroll
            for (int kk = 0; kk < 16; kk++) {
                uint32_t b0 = __float_as_uint(bp[kk * 8 + tig]);
                uint32_t b1 = __float_as_uint(bp[kk * 8 + tig + 4]);
                mma_tf32(c[nt][0], c[nt][1], c[nt][2], c[nt][3],
                         a0[kk], a1[kk], a2[kk], a3[kk], b0, b1);
            }
        }
    }

    __syncthreads();
    #pragma unroll
    for (int nt = 0; nt < 16; nt++) {
        int n0 = nt * 8 + tig * 2;
        As[n0 * NF_STRIDE + w * 16 + g]           = c[nt][0];
        As[(n0 + 1) * NF_STRIDE + w * 16 + g]     = c[nt][1];
        As[n0 * NF_STRIDE + w * 16 + 8 + g]       = c[nt][2];
        As[(n0 + 1) * NF_STRIDE + w * 16 + 8 + g] = c[nt][3];
    }
    __syncthreads();
    for (int q = tid; q < 4096; q += 256) {
        int n = q >> 5, kq = q & 31;
        int gn = nbase + n;
        if (gn < NN) {
            float4 v = *(const float4*)&As[n * NF_STRIDE + kq * 4];
            float4 bb = *(const float4*)&bsm[kq * 4];
            *(float4*)&g_h[(size_t)gn * DD + kq * 4] =
                make_float4(v.x + bb.x, v.y + bb.y, v.z + bb.z, v.w + bb.w);
        }
    }
}

// ---------------- CSR build ----------------
__global__ void k_hist(const int* __restrict__ dst)
{
    int e = blockIdx.x * 256 + threadIdx.x;
    if (e < EE) atomicAdd(&g_deg[dst[e]], 1);
}

__global__ void __launch_bounds__(1024) k_scan()
{
    int tid = threadIdx.x;
    int lane = tid & 31, w = tid >> 5;
    int base = tid * 20;
    int loc[20]; int s = 0;
    #pragma unroll
    for (int j = 0; j < 20; j++) {
        int n = base + j;
        int d = (n < NN) ? g_deg[n] : 0;
        loc[j] = s; s += d;
    }
    int v = s;
    #pragma unroll
    for (int off = 1; off < 32; off <<= 1) {
        int u = __shfl_up_sync(0xffffffffu, v, off);
        if (lane >= off) v += u;
    }
    __shared__ int wsum[32];
    if (lane == 31) wsum[w] = v;
    __syncthreads();
    if (w == 0) {
        int t = wsum[lane];
        #pragma unroll
        for (int off = 1; off < 32; off <<= 1) {
            int u = __shfl_up_sync(0xffffffffu, t, off);
            if (lane >= off) t += u;
        }
        wsum[lane] = t;
    }
    __syncthreads();
    int excl = v - s + (w > 0 ? wsum[w - 1] : 0);
    #pragma unroll
    for (int j = 0; j < 20; j++) {
        int n = base + j;
        if (n < NN) { int o = excl + loc[j]; g_off[n] = o; g_cur[n] = o; }
    }
}

__global__ void k_fill(const int* __restrict__ src, const int* __restrict__ dst)
{
    int e = blockIdx.x * 256 + threadIdx.x;
    if (e < EE) {
        int d = dst[e];
        int pos = atomicAdd(&g_cur[d], 1);
        g_epack[pos] = make_int2(src[e], e);
    }
}

// ---------------- kernel B: tensor-core (mma.sync tf32) edge MLP -> g_eg4f[.xyz] ----------------
// 3-stage cp.async pipeline; B pair-packed (conflict-free float2 LDS.64)
#define BP_STRIDE 72
#define A_STRIDE  68
#define A_BUF_F   (128 * A_STRIDE)          // 8704 floats
#define OFF_EPI   27648
#define OFF_A     (27648 + 768)
#define SMEM_MLP  ((27648 + 768 + 3 * A_BUF_F) * 4)

__global__ void __launch_bounds__(768, 1) k_mlp(const float* __restrict__ ef,
                                                const float* __restrict__ W2,
                                                const float* __restrict__ b2)
{
    extern __shared__ float sm[];
    float*  Bp  = sm;
    float2* epi = (float2*)(sm + OFF_EPI);
    float*  As  = sm + OFF_A;

    int tid = threadIdx.x;
    int wid = tid >> 5, lane = tid & 31;
    int g = lane >> 2, tig = lane & 3;
    int m = wid >> 3;          // head 0..2
    int r = wid & 7;           // row slice 0..7
    int rowbase = r * 16;

    // pair-packed B: Bp[n*72 + kk*8 + t*2 + {0: col t, 1: col t+4}]
    for (int i = tid; i < 384 * 64; i += 768) {
        int n = i >> 6, k = i & 63;
        int kk = k >> 3, t = k & 7;
        int pos = (t < 4) ? (n * BP_STRIDE + kk * 8 + t * 2)
                          : (n * BP_STRIDE + kk * 8 + (t - 4) * 2 + 1);
        Bp[pos] = g_B[i];
    }
    if (tid < 384) epi[tid] = make_float2(g_bb[tid], __ldg(W2 + tid));
    __syncthreads();

    float b2m = __ldg(b2 + m);

    int t0 = blockIdx.x;
    // prologue: stages 0 and 1
    #pragma unroll
    for (int p = 0; p < 2; p++) {
        int tp = t0 + p * GRID_MLP;
        if (tp < NTILES) {
            const float* srcb = ef + (size_t)tp * 8192;
            float* dstb = As + p * A_BUF_F;
            for (int c = tid; c < 2048; c += 768)
                cp16(dstb + (c >> 4) * A_STRIDE + (c & 15) * 4, srcb + c * 4);
        }
        CP_COMMIT;
    }

    int buf = 0;
    for (int t = t0; t < NTILES; t += GRID_MLP) {
        int tn = t + 2 * GRID_MLP;
        if (tn < NTILES) {
            const float* srcb = ef + (size_t)tn * 8192;
            int slot = buf + 2; if (slot >= 3) slot -= 3;
            float* dstb = As + slot * A_BUF_F;
            for (int c = tid; c < 2048; c += 768)
                cp16(dstb + (c >> 4) * A_STRIDE + (c & 15) * 4, srcb + c * 4);
        }
        CP_COMMIT;
        CP_WAIT2;              // oldest group (current buf) complete
        __syncthreads();

        const float* A = As + buf * A_BUF_F;
        const float* r0p = A + (rowbase + g) * A_STRIDE;
        const float* r1p = A + (rowbase + g + 8) * A_STRIDE;
        uint32_t a0[8], a1[8], a2[8], a3[8];
        #pragma unroll
        for (int kk = 0; kk < 8; kk++) {
            a0[kk] = __float_as_uint(r0p[kk * 8 + tig]);
            a2[kk] = __float_as_uint(r0p[kk * 8 + tig + 4]);
            a1[kk] = __float_as_uint(r1p[kk * 8 + tig]);
            a3[kk] = __float_as_uint(r1p[kk * 8 + tig + 4]);
        }

        float p0 = 0.f, p1 = 0.f;
        #pragma unroll 4
        for (int nt = 0; nt < 16; nt++) {
            int n0 = m * 128 + nt * 8;
            float c0 = 0.f, c1 = 0.f, c2 = 0.f, c3 = 0.f;
            const float2* bp = (const float2*)(Bp + (n0 + g) * BP_STRIDE) + tig;
            #pragma unroll
            for (int kk = 0; kk < 8; kk++) {
                float2 bv = bp[kk * 4];
                uint32_t b0 = __float_as_uint(bv.x);
                uint32_t b1 = __float_as_uint(bv.y);
                mma_tf32(c0, c1, c2, c3, a0[kk], a1[kk], a2[kk], a3[kk], b0, b1);
            }
            float2 e0 = epi[n0 + 2 * tig];
            float2 e1 = epi[n0 + 2 * tig + 1];
            p0 += fmaxf(c0 + e0.x, 0.f) * e0.y + fmaxf(c1 + e1.x, 0.f) * e1.y;
            p1 += fmaxf(c2 + e0.x, 0.f) * e0.y + fmaxf(c3 + e1.x, 0.f) * e1.y;
        }
        #pragma unroll
        for (int off = 1; off <= 2; off <<= 1) {
            p0 += __shfl_xor_sync(0xffffffffu, p0, off);
            p1 += __shfl_xor_sync(0xffffffffu, p1, off);
        }
        if (tig == 0) {
            int e = t * 128 + rowbase + g;
            g_eg4f[(size_t)(e)     * 4 + m] = __expf(sigmoidf_(p0 + b2m));
            g_eg4f[(size_t)(e + 8) * 4 + m] = __expf(sigmoidf_(p1 + b2m));
        }
        __syncthreads();
        buf++; if (buf >= 3) buf = 0;
    }
}

// ---------------- kernel C: gather (warp per dst node; batched epack via shfl) ----------------
__global__ void __launch_bounds__(256) k_gather()
{
    int n = (blockIdx.x * 256 + threadIdx.x) >> 5;
    int lane = threadIdx.x & 31;
    if (n >= NN) return;

    int off = g_off[n];
    int deg = g_deg[n];
    float4 hd = *(const float4*)&g_h[(size_t)n * DD + lane * 4];

    float4 aP = make_float4(0.f,0.f,0.f,0.f), q0 = aP, q1 = aP, q2 = aP;
    float za = 0.f, z0 = 0.f, z1 = 0.f, z2 = 0.f;

    int j = 0;
    while (j < deg) {
        int cnt = min(deg - j, 32);
        long long my = 0;
        if (lane < cnt) {
            int2 se = __ldg(&g_epack[off + j + lane]);
            my = ((long long)se.y << 32) | (unsigned int)se.x;
        }
        int jj = 0;
        int u4 = cnt & ~3;
        for (; jj < u4; jj += 4) {
            float4 hs[4], eg[4]; float p[4];
            #pragma unroll
            for (int u = 0; u < 4; u++) {
                long long pk = __shfl_sync(0xffffffffu, my, jj + u);
                int s = (int)(unsigned int)pk;
                int e = (int)(pk >> 32);
                hs[u] = *(const float4*)&g_h[(size_t)s * DD + lane * 4];
                eg[u] = *(const float4*)&g_eg4f[(size_t)e * 4];
                p[u] = hs[u].x*hd.x + hs[u].y*hd.y + hs[u].z*hd.z + hs[u].w*hd.w;
            }
            #pragma unroll
            for (int o = 16; o; o >>= 1) {
                #pragma unroll
                for (int u = 0; u < 4; u++) p[u] += __shfl_xor_sync(0xffffffffu, p[u], o);
            }
            #pragma unroll
            for (int u = 0; u < 4; u++) {
                float ea = __expf(p[u]);
                za += ea; z0 += eg[u].x; z1 += eg[u].y; z2 += eg[u].z;
                aP.x += ea*hs[u].x; aP.y += ea*hs[u].y; aP.z += ea*hs[u].z; aP.w += ea*hs[u].w;
                q0.x += eg[u].x*hs[u].x; q0.y += eg[u].x*hs[u].y; q0.z += eg[u].x*hs[u].z; q0.w += eg[u].x*hs[u].w;
                q1.x += eg[u].y*hs[u].x; q1.y += eg[u].y*hs[u].y; q1.z += eg[u].y*hs[u].z; q1.w += eg[u].y*hs[u].w;
                q2.x += eg[u].z*hs[u].x; q2.y += eg[u].z*hs[u].y; q2.z += eg[u].z*hs[u].z; q2.w += eg[u].z*hs[u].w;
            }
        }
        for (; jj < cnt; jj++) {
            long long pk = __shfl_sync(0xffffffffu, my, jj);
            int s = (int)(unsigned int)pk;
            int e = (int)(pk >> 32);
            float4 hs = *(const float4*)&g_h[(size_t)s * DD + lane * 4];
            float4 eg = *(const float4*)&g_eg4f[(size_t)e * 4];
            float pa = hs.x*hd.x + hs.y*hd.y + hs.z*hd.z + hs.w*hd.w;
            #pragma unroll
            for (int o = 16; o; o >>= 1) pa += __shfl_xor_sync(0xffffffffu, pa, o);
            float ea = __expf(pa);
            za += ea; z0 += eg.x; z1 += eg.y; z2 += eg.z;
            aP.x += ea*hs.x; aP.y += ea*hs.y; aP.z += ea*hs.z; aP.w += ea*hs.w;
            q0.x += eg.x*hs.x; q0.y += eg.x*hs.y; q0.z += eg.x*hs.z; q0.w += eg.x*hs.w;
            q1.x += eg.y*hs.x; q1.y += eg.y*hs.y; q1.z += eg.y*hs.z; q1.w += eg.y*hs.w;
            q2.x += eg.z*hs.x; q2.y += eg.z*hs.y; q2.z += eg.z*hs.z; q2.w += eg.z*hs.w;
        }
        j += cnt;
    }

    float sP = 0.f, s0 = 0.f, s1 = 0.f, s2 = 0.f;
    if (deg > 0) {
        sP = 1.f / (3.f * za); s0 = 1.f / (3.f * z0);
        s1 = 1.f / (3.f * z1); s2 = 1.f / (3.f * z2);
    }
    float* base = g_acc + (size_t)n * 512;
    *(float4*)(base + lane * 4)       = make_float4(aP.x*sP, aP.y*sP, aP.z*sP, aP.w*sP);
    *(float4*)(base + 128 + lane * 4) = make_float4(q0.x*s0, q0.y*s0, q0.z*s0, q0.w*s0);
    *(float4*)(base + 256 + lane * 4) = make_float4(q1.x*s1, q1.y*s1, q1.z*s1, q1.w*s1);
    *(float4*)(base + 384 + lane * 4) = make_float4(q2.x*s2, q2.y*s2, q2.z*s2, q2.w*s2);
    if (lane == 0) g_za[n] = (deg > 0) ? za : 0.f;
}

// ---------------- kernel D: finalize per node (tf32 mma, NB=64, 2 CTA/SM) ----------------
#define FW_STRIDE 132
#define SMEM_FIN  ((16896 + 8448) * 4)

__global__ void __launch_bounds__(256, 2) k_final(const float* __restrict__ nf,
                                                  const float* __restrict__ outb,
                                                  const float* __restrict__ gW,
                                                  const float* __restrict__ gb,
                                                  float* __restrict__ out)
{
    extern __shared__ float sm[];
    float* WsT = sm;
    float* As  = sm + 16896;

    int tid = threadIdx.x;
    int w = tid >> 5, lane = tid & 31;
    int g = lane >> 2, tig = lane & 3;
    int nbase = blockIdx.x * NB;

    float c[8][4];
    #pragma unroll
    for (int i = 0; i < 8; i++) { c[i][0]=0.f; c[i][1]=0.f; c[i][2]=0.f; c[i][3]=0.f; }

    for (int ph = 0; ph < 4; ph++) {
        __syncthreads();   // prior mma done reading As/WsT
        // stage As raw via cp.async (HW truncates to tf32); zero-fill OOB
        for (int q = tid; q < 2048; q += 256) {
            int nn = q >> 5, kq = q & 31;
            int gn = nbase + nn;
            if (gn < NN) cp16(&As[nn * FW_STRIDE + kq * 4],
                              &g_acc[(size_t)gn * 512 + ph * 128 + kq * 4]);
            else *(float4*)&As[nn * FW_STRIDE + kq * 4] = make_float4(0.f,0.f,0.f,0.f);
        }
        #pragma unroll
        for (int pass = 0; pass < 2; pass++) {
            const float* Csrc = (pass ? g_Ct_lo : g_Ct_hi) + ph * 16384;
            for (int q = tid; q < 4096; q += 256) {
                int rr = q >> 5, kq = q & 31;
                cp16(&WsT[rr * FW_STRIDE + kq * 4], &Csrc[rr * 128 + kq * 4]);
            }
            CP_COMMIT; CP_WAIT0;
            __syncthreads();
            uint32_t a0[16], a1[16], a2[16], a3[16];
            const float* w0 = &WsT[(w * 16 + g) * FW_STRIDE];
            const float* w1 = &WsT[(w * 16 + 8 + g) * FW_STRIDE];
            #pragma unroll
            for (int kk = 0; kk < 16; kk++) {
                a0[kk] = __float_as_uint(w0[kk * 8 + tig]);
                a2[kk] = __float_as_uint(w0[kk * 8 + tig + 4]);
                a1[kk] = __float_as_uint(w1[kk * 8 + tig]);
                a3[kk] = __float_as_uint(w1[kk * 8 + tig + 4]);
            }
            #pragma unroll
            for (int nt = 0; nt < 8; nt++) {
                const float* bp = &As[(nt * 8 + g) * FW_STRIDE];
                #pragma unroll
                for (int kk = 0; kk < 16; kk++) {
                    uint32_t b0 = __float_as_uint(bp[kk * 8 + tig]);
                    uint32_t b1 = __float_as_uint(bp[kk * 8 + tig + 4]);
                    mma_tf32(c[nt][0], c[nt][1], c[nt][2], c[nt][3],
                             a0[kk], a1[kk], a2[kk], a3[kk], b0, b1);
                }
            }
            if (pass == 0) __syncthreads();   // before overwriting WsT with lo
        }
    }

    __syncthreads();
    #pragma unroll
    for (int nt = 0; nt < 8; nt++) {
        int n0 = nt * 8 + tig * 2;
        As[n0 * FW_STRIDE + w * 16 + g]           = c[nt][0];
        As[(n0 + 1) * FW_STRIDE + w * 16 + g]     = c[nt][1];
        As[n0 * FW_STRIDE + w * 16 + 8 + g]       = c[nt][2];
        As[(n0 + 1) * FW_STRIDE + w * 16 + 8 + g] = c[nt][3];
    }
    __syncthreads();

    float4 b4  = *(const float4*)&outb[lane * 4];
    float4 gw4 = *(const float4*)&gW[lane * 4];
    float gb0 = __ldg(gb);
    #pragma unroll
    for (int t = 0; t < 8; t++) {
        int i = w * 8 + t;
        int n = nbase + i;
        if (n >= NN) break;
        float4 vv = *(const float4*)&As[i * FW_STRIDE + lane * 4];
        bool ok = (g_za[n] > 0.f);
        float4 pre = make_float4(fmaxf(vv.x + b4.x, 0.f), fmaxf(vv.y + b4.y, 0.f),
                                 fmaxf(vv.z + b4.z, 0.f), fmaxf(vv.w + b4.w, 0.f));
        float4 hv  = *(const float4*)&g_h[(size_t)n * DD + lane * 4];
        float4 ho  = ok ? pre : hv;
        float4 nfv = *(const float4*)&nf[(size_t)n * DD + lane * 4];
        float gp = nfv.x * gw4.x + nfv.y * gw4.y + nfv.z * gw4.z + nfv.w * gw4.w;
        #pragma unroll
        for (int o = 16; o; o >>= 1) gp += __shfl_xor_sync(0xffffffffu, gp, o);
        float gate = sigmoidf_(gp + gb0);
        float4 oo = make_float4(gate * ho.x + (1.f - gate) * nfv.x,
                                gate * ho.y + (1.f - gate) * nfv.y,
                                gate * ho.z + (1.f - gate) * nfv.z,
                                gate * ho.w + (1.f - gate) * nfv.w);
        *(float4*)&out[(size_t)n * DD + lane * 4] = oo;
    }
}

// ---------------- launcher ----------------
extern "C" void kernel_launch(void* const* d_in, const int* in_sizes, int n_in,
                              void* d_out, int out_size)
{
    const float* nf   = (const float*)d_in[0];
    const float* ef   = (const float*)d_in[1];
    const int*   src  = (const int*)  d_in[2];
    const int*   dst  = (const int*)  d_in[3];
    const float* natt = (const float*)d_in[4];
    const float* relW = (const float*)d_in[5];
    const float* W1   = (const float*)d_in[6];
    const float* b1   = (const float*)d_in[7];
    const float* W2   = (const float*)d_in[8];
    const float* b2   = (const float*)d_in[9];
    const float* nfcW = (const float*)d_in[10];
    const float* nfcb = (const float*)d_in[11];
    const float* efcW = (const float*)d_in[12];
    const float* efcb = (const float*)d_in[13];
    const float* outW = (const float*)d_in[14];
    const float* outb = (const float*)d_in[15];
    const float* gW   = (const float*)d_in[16];
    const float* gb   = (const float*)d_in[17];
    float* out = (float*)d_out;

    static cudaStream_t s_side = nullptr;
    static cudaEvent_t e_fork = nullptr, e_prepF = nullptr, e_fill = nullptr, e_comb = nullptr;
    if (s_side == nullptr) {
        cudaStreamCreateWithFlags(&s_side, cudaStreamNonBlocking);
        cudaEventCreateWithFlags(&e_fork,  cudaEventDisableTiming);
        cudaEventCreateWithFlags(&e_prepF, cudaEventDisableTiming);
        cudaEventCreateWithFlags(&e_fill,  cudaEventDisableTiming);
        cudaEventCreateWithFlags(&e_comb,  cudaEventDisableTiming);
    }

    void* pDeg;
    cudaGetSymbolAddress(&pDeg, g_deg);

    cudaFuncSetAttribute(k_node_fc, cudaFuncAttributeMaxDynamicSharedMemorySize, SMEM_NFC);
    cudaFuncSetAttribute(k_mlp,     cudaFuncAttributeMaxDynamicSharedMemorySize, SMEM_MLP);
    cudaFuncSetAttribute(k_final,   cudaFuncAttributeMaxDynamicSharedMemorySize, SMEM_FIN);

    // fork: prepF + CSR build + combine on side stream
    cudaEventRecord(e_fork, 0);
    cudaStreamWaitEvent(s_side, e_fork, 0);
    k_prepF<<<192, 128, 0, s_side>>>(efcW, efcb, W1, b1);
    cudaEventRecord(e_prepF, s_side);
    cudaMemsetAsync(pDeg, 0, NN * sizeof(int), s_side);
    k_hist<<<(EE + 255) / 256, 256, 0, s_side>>>(dst);
    k_scan<<<1, 1024, 0, s_side>>>();
    k_fill<<<(EE + 255) / 256, 256, 0, s_side>>>(src, dst);
    cudaEventRecord(e_fill, s_side);
    k_combine<<<512, 128, 0, s_side>>>(natt, relW, outW);
    cudaEventRecord(e_comb, s_side);

    // main chain
    k_prepW<<<128, 128>>>(nfcW);
    k_node_fc<<<(NN + 127) / 128, 256, SMEM_NFC>>>(nf, nfcb);
    cudaStreamWaitEvent(0, e_prepF, 0);
    k_mlp<<<GRID_MLP, 768, SMEM_MLP>>>(ef, W2, b2);

    // join: gather needs CSR + mlp + h; final needs combine
    cudaStreamWaitEvent(0, e_fill, 0);
    k_gather<<<(NN + 7) / 8, 256>>>();
    cudaStreamWaitEvent(0, e_comb, 0);
    k_final<<<(NN + NB - 1) / NB, 256, SMEM_FIN>>>(nf, outb, gW, gb, out);
}

// round 16
// speedup vs baseline: 1.3246x; 1.1156x over previous
#include <cuda_runtime.h>
#include <cuda_bf16.h>
#include <math.h>
#include <stdint.h>

#define NN   20000
#define NNP  20032
#define EE   320000
#define DD   128
#define DEH  64
#define NTILES (EE / 128)   // 2500
#define GRID_MLP 148
#define NB   64             // nodes per k_final CTA (2 CTA/SM — wave-balanced)

// ---------------- scratch (device globals; no allocation allowed) ----------------
__device__ float g_h[NN * DD];                 // node_fc output h
__device__ float g_acc[(size_t)NNP * 512];     // per-node [P | Q0 | Q1 | Q2] (pre-scaled)
__device__ float g_za[NNP];                    // sum exp(a) per dst (mask)
__device__ float g_Ct_hi[4 * DD * DD];         // folded C, transposed [ph][out][k], tf32 hi
__device__ float g_Wt_hi[DD * DD];             // node_fc W transposed [out][k], tf32 hi
__device__ float g_Wt_lo[DD * DD];             // tf32 lo residual
__device__ float g_eg4f[(size_t)EE * 4];       // [e] = {eg0, eg1, eg2, -}
__device__ float g_B[384 * 64];                // folded MLP weights Gᵀ (tf32-rounded fp32)
__device__ float g_bb[384];                    // folded bias bb1
__device__ int   g_deg[NN];
__device__ int   g_off[NN];
__device__ int   g_cur[NN];
__device__ int2  g_epack[EE];                  // (src, e) sorted by dst

__device__ __forceinline__ float sigmoidf_(float x) { return 1.f / (1.f + __expf(-x)); }

__device__ __forceinline__ uint32_t smem_to_u32(const void* p) {
    uint32_t a;
    asm("{ .reg .u64 t; cvta.to.shared.u64 t, %1; cvt.u32.u64 %0, t; }" : "=r"(a) : "l"(p));
    return a;
}
__device__ __forceinline__ uint32_t tf32_rna(float x) {
    uint32_t r; asm("cvt.rna.tf32.f32 %0, %1;" : "=r"(r) : "f"(x)); return r;
}
__device__ __forceinline__ float tf32f(float x) { return __uint_as_float(tf32_rna(x)); }
__device__ __forceinline__ void mma_tf32(float& c0, float& c1, float& c2, float& c3,
                                         uint32_t a0, uint32_t a1, uint32_t a2, uint32_t a3,
                                         uint32_t b0, uint32_t b1) {
    asm volatile("mma.sync.aligned.m16n8k8.row.col.f32.tf32.tf32.f32 "
                 "{%0,%1,%2,%3}, {%4,%5,%6,%7}, {%8,%9}, {%0,%1,%2,%3};"
                 : "+f"(c0), "+f"(c1), "+f"(c2), "+f"(c3)
                 : "r"(a0), "r"(a1), "r"(a2), "r"(a3), "r"(b0), "r"(b1));
}
__device__ __forceinline__ void cp16(float* dst_smem, const float* src) {
    uint32_t d = smem_to_u32(dst_smem);
    asm volatile("cp.async.ca.shared.global [%0], [%1], 16;" :: "r"(d), "l"(src));
}
#define CP_COMMIT asm volatile("cp.async.commit_group;" ::: "memory")
#define CP_WAIT2  asm volatile("cp.async.wait_group 2;"  ::: "memory")
#define CP_WAIT0  asm volatile("cp.async.wait_group 0;"  ::: "memory")

// ---------------- prepW (critical path, tiny): node_fc weight transpose + split ----------------
__global__ void __launch_bounds__(128) k_prepW(const float* __restrict__ nfcW)
{
    int k = blockIdx.x, c = threadIdx.x;
    float v = nfcW[k * DD + c];
    float hi = tf32f(v);
    g_Wt_hi[c * DD + k] = hi;
    g_Wt_lo[c * DD + k] = tf32f(v - hi);
}

// ---------------- prepF (side stream): fold G = efcW @ W1 (tf32) + bias ----------------
__global__ void __launch_bounds__(128) k_prepF(const float* __restrict__ efcW,
                                               const float* __restrict__ efcb,
                                               const float* __restrict__ W1,
                                               const float* __restrict__ b1)
{
    __shared__ float sW[4096];   // transposed efcW: sW[fp*64 + k]
    int tid = threadIdx.x;
    for (int i = tid; i < 4096; i += 128) {
        int k = i >> 6, fp = i & 63;
        sW[fp * 64 + k] = efcW[i];
    }
    __syncthreads();
    int half = tid >> 6;
    int k = tid & 63;
    int n = blockIdx.x * 2 + half;
    int m = n >> 7, f = n & 127;
    float acc = 0.f;
    float bacc = b1[n];
    #pragma unroll 4
    for (int fp = 0; fp < DEH; fp++) {
        float w1v = __ldg(&W1[(m * DEH + fp) * DD + f]);
        acc += sW[fp * 64 + k] * w1v;
        bacc += __ldg(&efcb[fp]) * w1v;
    }
    g_B[n * 64 + k] = tf32f(acc);
    if (k == 0) g_bb[n] = bacc;
}

// ---------------- combine (side stream): C0 = Wsum@U_top, Cm = W_m@U_bot ----------------
__global__ void __launch_bounds__(128) k_combine(const float* __restrict__ natt,
                                                 const float* __restrict__ relW,
                                                 const float* __restrict__ outW)
{
    __shared__ float row[DD];
    int i = blockIdx.x >> 7;          // phase 0..3
    int d = blockIdx.x & 127;         // k
    int c = threadIdx.x;              // output
    if (i == 0)
        row[c] = natt[d * DD + c] + natt[DD * DD + d * DD + c] + natt[2 * DD * DD + d * DD + c];
    else
        row[c] = relW[(i - 1) * DD * DD + d * DD + c];
    __syncthreads();
    const float* U = (i == 0) ? outW : outW + DD * DD;
    float acc = 0.f;
    #pragma unroll 8
    for (int f = 0; f < DD; f++) acc += row[f] * U[f * DD + c];
    g_Ct_hi[i * DD * DD + c * DD + d] = tf32f(acc);
}

// ---------------- kernel A: h = nf @ node_fc_W + b  (tf32 mma, 3-pass compensated) ----------------
#define NF_STRIDE 132
#define SMEM_NFC ((16896 * 2 + 128) * 4)

__global__ void __launch_bounds__(256, 1) k_node_fc(const float* __restrict__ nf,
                                                    const float* __restrict__ b)
{
    extern __shared__ float sm[];
    float* Ws  = sm;
    float* As  = sm + 16896;
    float* bsm = sm + 2 * 16896;

    int tid = threadIdx.x;
    int w = tid >> 5, lane = tid & 31;
    int g = lane >> 2, tig = lane & 3;
    int nbase = blockIdx.x * 128;
    if (tid < 128) bsm[tid] = b[tid];

    float c[16][4];
    #pragma unroll
    for (int i = 0; i < 16; i++) { c[i][0]=0.f; c[i][1]=0.f; c[i][2]=0.f; c[i][3]=0.f; }

    #pragma unroll
    for (int pass = 0; pass < 3; pass++) {
        __syncthreads();
        if (pass != 1) {
            bool lo = (pass == 2);
            for (int q = tid; q < 4096; q += 256) {
                int n = q >> 5, kq = q & 31;
                int gn = nbase + n;
                float4 v = make_float4(0.f,0.f,0.f,0.f);
                if (gn < NN) v = *(const float4*)&nf[(size_t)gn * DD + kq * 4];
                float4 o;
                if (!lo) o = make_float4(tf32f(v.x), tf32f(v.y), tf32f(v.z), tf32f(v.w));
                else     o = make_float4(tf32f(v.x - tf32f(v.x)), tf32f(v.y - tf32f(v.y)),
                                         tf32f(v.z - tf32f(v.z)), tf32f(v.w - tf32f(v.w)));
                *(float4*)&As[n * NF_STRIDE + kq * 4] = o;
            }
        }
        const float* Wsrc = (pass == 1) ? g_Wt_lo : g_Wt_hi;
        for (int q = tid; q < 4096; q += 256) {
            int rr = q >> 5, kq = q & 31;
            cp16(&Ws[rr * NF_STRIDE + kq * 4], &Wsrc[rr * DD + kq * 4]);
        }
        CP_COMMIT; CP_WAIT0;
        __syncthreads();

        uint32_t a0[16], a1[16], a2[16], a3[16];
        const float* w0 = &Ws[(w * 16 + g) * NF_STRIDE];
        const float* w1 = &Ws[(w * 16 + 8 + g) * NF_STRIDE];
        #pragma unroll
        for (int kk = 0; kk < 16; kk++) {
            a0[kk] = __float_as_uint(w0[kk * 8 + tig]);
            a2[kk] = __float_as_uint(w0[kk * 8 + tig + 4]);
            a1[kk] = __float_as_uint(w1[kk * 8 + tig]);
            a3[kk] = __float_as_uint(w1[kk * 8 + tig + 4]);
        }
        #pragma unroll
        for (int nt = 0; nt < 16; nt++) {
            const float* bp = &As[(nt * 8 + g) * NF_STRIDE];
            #pragma unroll
            for (int kk = 0; kk < 16; kk++) {
                uint32_t b0 = __float_as_uint(bp[kk * 8 + tig]);
                uint32_t b1 = __float_as_uint(bp[kk * 8 + tig + 4]);
                mma_tf32(c[nt][0], c[nt][1], c[nt][2], c[nt][3],
                         a0[kk], a1[kk], a2[kk], a3[kk], b0, b1);
            }
        }
    }

    __syncthreads();
    #pragma unroll
    for (int nt = 0; nt < 16; nt++) {
        int n0 = nt * 8 + tig * 2;
        As[n0 * NF_STRIDE + w * 16 + g]           = c[nt][0];
        As[(n0 + 1) * NF_STRIDE + w * 16 + g]     = c[nt][1];
        As[n0 * NF_STRIDE + w * 16 + 8 + g]       = c[nt][2];
        As[(n0 + 1) * NF_STRIDE + w * 16 + 8 + g] = c[nt][3];
    }
    __syncthreads();
    for (int q = tid; q < 4096; q += 256) {
        int n = q >> 5, kq = q & 31;
        int gn = nbase + n;
        if (gn < NN) {
            float4 v = *(const float4*)&As[n * NF_STRIDE + kq * 4];
            float4 bb = *(const float4*)&bsm[kq * 4];
            *(float4*)&g_h[(size_t)gn * DD + kq * 4] =
                make_float4(v.x + bb.x, v.y + bb.y, v.z + bb.z, v.w + bb.w);
        }
    }
}

// ---------------- CSR build ----------------
__global__ void k_hist(const int* __restrict__ dst)
{
    int e = blockIdx.x * 256 + threadIdx.x;
    if (e < EE) atomicAdd(&g_deg[dst[e]], 1);
}

__global__ void __launch_bounds__(1024) k_scan()
{
    int tid = threadIdx.x;
    int lane = tid & 31, w = tid >> 5;
    int base = tid * 20;
    int loc[20]; int s = 0;
    #pragma unroll
    for (int j = 0; j < 20; j++) {
        int n = base + j;
        int d = (n < NN) ? g_deg[n] : 0;
        loc[j] = s; s += d;
    }
    int v = s;
    #pragma unroll
    for (int off = 1; off < 32; off <<= 1) {
        int u = __shfl_up_sync(0xffffffffu, v, off);
        if (lane >= off) v += u;
    }
    __shared__ int wsum[32];
    if (lane == 31) wsum[w] = v;
    __syncthreads();
    if (w == 0) {
        int t = wsum[lane];
        #pragma unroll
        for (int off = 1; off < 32; off <<= 1) {
            int u = __shfl_up_sync(0xffffffffu, t, off);
            if (lane >= off) t += u;
        }
        wsum[lane] = t;
    }
    __syncthreads();
    int excl = v - s + (w > 0 ? wsum[w - 1] : 0);
    #pragma unroll
    for (int j = 0; j < 20; j++) {
        int n = base + j;
        if (n < NN) { int o = excl + loc[j]; g_off[n] = o; g_cur[n] = o; }
    }
}

__global__ void k_fill(const int* __restrict__ src, const int* __restrict__ dst)
{
    int e = blockIdx.x * 256 + threadIdx.x;
    if (e < EE) {
        int d = dst[e];
        int pos = atomicAdd(&g_cur[d], 1);
        g_epack[pos] = make_int2(src[e], e);
    }
}

// ---------------- kernel B: tensor-core (mma.sync tf32) edge MLP -> g_eg4f[.xyz] ----------------
// 3-stage cp.async pipeline; B pair-packed (conflict-free float2 LDS.64)
#define BP_STRIDE 72
#define A_STRIDE  68
#define A_BUF_F   (128 * A_STRIDE)          // 8704 floats
#define OFF_EPI   27648
#define OFF_A     (27648 + 768)
#define SMEM_MLP  ((27648 + 768 + 3 * A_BUF_F) * 4)

__global__ void __launch_bounds__(768, 1) k_mlp(const float* __restrict__ ef,
                                                const float* __restrict__ W2,
                                                const float* __restrict__ b2)
{
    extern __shared__ float sm[];
    float*  Bp  = sm;
    float2* epi = (float2*)(sm + OFF_EPI);
    float*  As  = sm + OFF_A;

    int tid = threadIdx.x;
    int wid = tid >> 5, lane = tid & 31;
    int g = lane >> 2, tig = lane & 3;
    int m = wid >> 3;          // head 0..2
    int r = wid & 7;           // row slice 0..7
    int rowbase = r * 16;

    // pair-packed B: Bp[n*72 + kk*8 + t*2 + {0: col t, 1: col t+4}]
    for (int i = tid; i < 384 * 64; i += 768) {
        int n = i >> 6, k = i & 63;
        int kk = k >> 3, t = k & 7;
        int pos = (t < 4) ? (n * BP_STRIDE + kk * 8 + t * 2)
                          : (n * BP_STRIDE + kk * 8 + (t - 4) * 2 + 1);
        Bp[pos] = g_B[i];
    }
    if (tid < 384) epi[tid] = make_float2(g_bb[tid], __ldg(W2 + tid));
    __syncthreads();

    float b2m = __ldg(b2 + m);

    int t0 = blockIdx.x;
    // prologue: stages 0 and 1
    #pragma unroll
    for (int p = 0; p < 2; p++) {
        int tp = t0 + p * GRID_MLP;
        if (tp < NTILES) {
            const float* srcb = ef + (size_t)tp * 8192;
            float* dstb = As + p * A_BUF_F;
            for (int c = tid; c < 2048; c += 768)
                cp16(dstb + (c >> 4) * A_STRIDE + (c & 15) * 4, srcb + c * 4);
        }
        CP_COMMIT;
    }

    int buf = 0;
    for (int t = t0; t < NTILES; t += GRID_MLP) {
        int tn = t + 2 * GRID_MLP;
        if (tn < NTILES) {
            const float* srcb = ef + (size_t)tn * 8192;
            int slot = buf + 2; if (slot >= 3) slot -= 3;
            float* dstb = As + slot * A_BUF_F;
            for (int c = tid; c < 2048; c += 768)
                cp16(dstb + (c >> 4) * A_STRIDE + (c & 15) * 4, srcb + c * 4);
        }
        CP_COMMIT;
        CP_WAIT2;              // oldest group (current buf) complete
        __syncthreads();

        const float* A = As + buf * A_BUF_F;
        const float* r0p = A + (rowbase + g) * A_STRIDE;
        const float* r1p = A + (rowbase + g + 8) * A_STRIDE;
        uint32_t a0[8], a1[8], a2[8], a3[8];
        #pragma unroll
        for (int kk = 0; kk < 8; kk++) {
            a0[kk] = __float_as_uint(r0p[kk * 8 + tig]);
            a2[kk] = __float_as_uint(r0p[kk * 8 + tig + 4]);
            a1[kk] = __float_as_uint(r1p[kk * 8 + tig]);
            a3[kk] = __float_as_uint(r1p[kk * 8 + tig + 4]);
        }

        float p0 = 0.f, p1 = 0.f;
        #pragma unroll 4
        for (int nt = 0; nt < 16; nt++) {
            int n0 = m * 128 + nt * 8;
            float c0 = 0.f, c1 = 0.f, c2 = 0.f, c3 = 0.f;
            const float2* bp = (const float2*)(Bp + (n0 + g) * BP_STRIDE) + tig;
            #pragma unroll
            for (int kk = 0; kk < 8; kk++) {
                float2 bv = bp[kk * 4];
                uint32_t b0 = __float_as_uint(bv.x);
                uint32_t b1 = __float_as_uint(bv.y);
                mma_tf32(c0, c1, c2, c3, a0[kk], a1[kk], a2[kk], a3[kk], b0, b1);
            }
            float2 e0 = epi[n0 + 2 * tig];
            float2 e1 = epi[n0 + 2 * tig + 1];
            p0 += fmaxf(c0 + e0.x, 0.f) * e0.y + fmaxf(c1 + e1.x, 0.f) * e1.y;
            p1 += fmaxf(c2 + e0.x, 0.f) * e0.y + fmaxf(c3 + e1.x, 0.f) * e1.y;
        }
        #pragma unroll
        for (int off = 1; off <= 2; off <<= 1) {
            p0 += __shfl_xor_sync(0xffffffffu, p0, off);
            p1 += __shfl_xor_sync(0xffffffffu, p1, off);
        }
        if (tig == 0) {
            int e = t * 128 + rowbase + g;
            g_eg4f[(size_t)(e)     * 4 + m] = __expf(sigmoidf_(p0 + b2m));
            g_eg4f[(size_t)(e + 8) * 4 + m] = __expf(sigmoidf_(p1 + b2m));
        }
        __syncthreads();
        buf++; if (buf >= 3) buf = 0;
    }
}

// ---------------- kernel C: gather (warp per dst node; batched epack via shfl) ----------------
__global__ void __launch_bounds__(256) k_gather()
{
    int n = (blockIdx.x * 256 + threadIdx.x) >> 5;
    int lane = threadIdx.x & 31;
    if (n >= NN) return;

    int off = g_off[n];
    int deg = g_deg[n];
    float4 hd = *(const float4*)&g_h[(size_t)n * DD + lane * 4];

    float4 aP = make_float4(0.f,0.f,0.f,0.f), q0 = aP, q1 = aP, q2 = aP;
    float za = 0.f, z0 = 0.f, z1 = 0.f, z2 = 0.f;

    int j = 0;
    while (j < deg) {
        int cnt = min(deg - j, 32);
        long long my = 0;
        if (lane < cnt) {
            int2 se = __ldg(&g_epack[off + j + lane]);
            my = ((long long)se.y << 32) | (unsigned int)se.x;
        }
        int jj = 0;
        int u4 = cnt & ~3;
        for (; jj < u4; jj += 4) {
            float4 hs[4], eg[4]; float p[4];
            #pragma unroll
            for (int u = 0; u < 4; u++) {
                long long pk = __shfl_sync(0xffffffffu, my, jj + u);
                int s = (int)(unsigned int)pk;
                int e = (int)(pk >> 32);
                hs[u] = *(const float4*)&g_h[(size_t)s * DD + lane * 4];
                eg[u] = *(const float4*)&g_eg4f[(size_t)e * 4];
                p[u] = hs[u].x*hd.x + hs[u].y*hd.y + hs[u].z*hd.z + hs[u].w*hd.w;
            }
            #pragma unroll
            for (int o = 16; o; o >>= 1) {
                #pragma unroll
                for (int u = 0; u < 4; u++) p[u] += __shfl_xor_sync(0xffffffffu, p[u], o);
            }
            #pragma unroll
            for (int u = 0; u < 4; u++) {
                float ea = __expf(p[u]);
                za += ea; z0 += eg[u].x; z1 += eg[u].y; z2 += eg[u].z;
                aP.x += ea*hs[u].x; aP.y += ea*hs[u].y; aP.z += ea*hs[u].z; aP.w += ea*hs[u].w;
                q0.x += eg[u].x*hs[u].x; q0.y += eg[u].x*hs[u].y; q0.z += eg[u].x*hs[u].z; q0.w += eg[u].x*hs[u].w;
                q1.x += eg[u].y*hs[u].x; q1.y += eg[u].y*hs[u].y; q1.z += eg[u].y*hs[u].z; q1.w += eg[u].y*hs[u].w;
                q2.x += eg[u].z*hs[u].x; q2.y += eg[u].z*hs[u].y; q2.z += eg[u].z*hs[u].z; q2.w += eg[u].z*hs[u].w;
            }
        }
        for (; jj < cnt; jj++) {
            long long pk = __shfl_sync(0xffffffffu, my, jj);
            int s = (int)(unsigned int)pk;
            int e = (int)(pk >> 32);
            float4 hs = *(const float4*)&g_h[(size_t)s * DD + lane * 4];
            float4 eg = *(const float4*)&g_eg4f[(size_t)e * 4];
            float pa = hs.x*hd.x + hs.y*hd.y + hs.z*hd.z + hs.w*hd.w;
            #pragma unroll
            for (int o = 16; o; o >>= 1) pa += __shfl_xor_sync(0xffffffffu, pa, o);
            float ea = __expf(pa);
            za += ea; z0 += eg.x; z1 += eg.y; z2 += eg.z;
            aP.x += ea*hs.x; aP.y += ea*hs.y; aP.z += ea*hs.z; aP.w += ea*hs.w;
            q0.x += eg.x*hs.x; q0.y += eg.x*hs.y; q0.z += eg.x*hs.z; q0.w += eg.x*hs.w;
            q1.x += eg.y*hs.x; q1.y += eg.y*hs.y; q1.z += eg.y*hs.z; q1.w += eg.y*hs.w;
            q2.x += eg.z*hs.x; q2.y += eg.z*hs.y; q2.z += eg.z*hs.z; q2.w += eg.z*hs.w;
        }
        j += cnt;
    }

    float sP = 0.f, s0 = 0.f, s1 = 0.f, s2 = 0.f;
    if (deg > 0) {
        sP = 1.f / (3.f * za); s0 = 1.f / (3.f * z0);
        s1 = 1.f / (3.f * z1); s2 = 1.f / (3.f * z2);
    }
    float* base = g_acc + (size_t)n * 512;
    *(float4*)(base + lane * 4)       = make_float4(aP.x*sP, aP.y*sP, aP.z*sP, aP.w*sP);
    *(float4*)(base + 128 + lane * 4) = make_float4(q0.x*s0, q0.y*s0, q0.z*s0, q0.w*s0);
    *(float4*)(base + 256 + lane * 4) = make_float4(q1.x*s1, q1.y*s1, q1.z*s1, q1.w*s1);
    *(float4*)(base + 384 + lane * 4) = make_float4(q2.x*s2, q2.y*s2, q2.z*s2, q2.w*s2);
    if (lane == 0) g_za[n] = (deg > 0) ? za : 0.f;
}

// ---------------- kernel D: finalize per node (tf32 mma hi-only, NB=64, 2 CTA/SM) ----------------
#define FW_STRIDE 132
#define SMEM_FIN  ((16896 + 8448) * 4)

__global__ void __launch_bounds__(256, 2) k_final(const float* __restrict__ nf,
                                                  const float* __restrict__ outb,
                                                  const float* __restrict__ gW,
                                                  const float* __restrict__ gb,
                                                  float* __restrict__ out)
{
    extern __shared__ float sm[];
    float* WsT = sm;
    float* As  = sm + 16896;

    int tid = threadIdx.x;
    int w = tid >> 5, lane = tid & 31;
    int g = lane >> 2, tig = lane & 3;
    int nbase = blockIdx.x * NB;

    float c[8][4];
    #pragma unroll
    for (int i = 0; i < 8; i++) { c[i][0]=0.f; c[i][1]=0.f; c[i][2]=0.f; c[i][3]=0.f; }

    for (int ph = 0; ph < 4; ph++) {
        __syncthreads();   // prior mma done reading As/WsT
        // stage As raw via cp.async (HW truncates to tf32); zero-fill OOB
        for (int q = tid; q < 2048; q += 256) {
            int nn = q >> 5, kq = q & 31;
            int gn = nbase + nn;
            if (gn < NN) cp16(&As[nn * FW_STRIDE + kq * 4],
                              &g_acc[(size_t)gn * 512 + ph * 128 + kq * 4]);
            else *(float4*)&As[nn * FW_STRIDE + kq * 4] = make_float4(0.f,0.f,0.f,0.f);
        }
        // stage C (hi only)
        {
            const float* Csrc = g_Ct_hi + ph * 16384;
            for (int q = tid; q < 4096; q += 256) {
                int rr = q >> 5, kq = q & 31;
                cp16(&WsT[rr * FW_STRIDE + kq * 4], &Csrc[rr * 128 + kq * 4]);
            }
        }
        CP_COMMIT; CP_WAIT0;
        __syncthreads();
        uint32_t a0[16], a1[16], a2[16], a3[16];
        const float* w0 = &WsT[(w * 16 + g) * FW_STRIDE];
        const float* w1 = &WsT[(w * 16 + 8 + g) * FW_STRIDE];
        #pragma unroll
        for (int kk = 0; kk < 16; kk++) {
            a0[kk] = __float_as_uint(w0[kk * 8 + tig]);
            a2[kk] = __float_as_uint(w0[kk * 8 + tig + 4]);
            a1[kk] = __float_as_uint(w1[kk * 8 + tig]);
            a3[kk] = __float_as_uint(w1[kk * 8 + tig + 4]);
        }
        #pragma unroll
        for (int nt = 0; nt < 8; nt++) {
            const float* bp = &As[(nt * 8 + g) * FW_STRIDE];
            #pragma unroll
            for (int kk = 0; kk < 16; kk++) {
                uint32_t b0 = __float_as_uint(bp[kk * 8 + tig]);
                uint32_t b1 = __float_as_uint(bp[kk * 8 + tig + 4]);
                mma_tf32(c[nt][0], c[nt][1], c[nt][2], c[nt][3],
                         a0[kk], a1[kk], a2[kk], a3[kk], b0, b1);
            }
        }
    }

    __syncthreads();
    #pragma unroll
    for (int nt = 0; nt < 8; nt++) {
        int n0 = nt * 8 + tig * 2;
        As[n0 * FW_STRIDE + w * 16 + g]           = c[nt][0];
        As[(n0 + 1) * FW_STRIDE + w * 16 + g]     = c[nt][1];
        As[n0 * FW_STRIDE + w * 16 + 8 + g]       = c[nt][2];
        As[(n0 + 1) * FW_STRIDE + w * 16 + 8 + g] = c[nt][3];
    }
    __syncthreads();

    float4 b4  = *(const float4*)&outb[lane * 4];
    float4 gw4 = *(const float4*)&gW[lane * 4];
    float gb0 = __ldg(gb);
    #pragma unroll
    for (int t = 0; t < 8; t++) {
        int i = w * 8 + t;
        int n = nbase + i;
        if (n >= NN) break;
        float4 vv = *(const float4*)&As[i * FW_STRIDE + lane * 4];
        bool ok = (g_za[n] > 0.f);
        float4 pre = make_float4(fmaxf(vv.x + b4.x, 0.f), fmaxf(vv.y + b4.y, 0.f),
                                 fmaxf(vv.z + b4.z, 0.f), fmaxf(vv.w + b4.w, 0.f));
        float4 hv  = *(const float4*)&g_h[(size_t)n * DD + lane * 4];
        float4 ho  = ok ? pre : hv;
        float4 nfv = *(const float4*)&nf[(size_t)n * DD + lane * 4];
        float gp = nfv.x * gw4.x + nfv.y * gw4.y + nfv.z * gw4.z + nfv.w * gw4.w;
        #pragma unroll
        for (int o = 16; o; o >>= 1) gp += __shfl_xor_sync(0xffffffffu, gp, o);
        float gate = sigmoidf_(gp + gb0);
        float4 oo = make_float4(gate * ho.x + (1.f - gate) * nfv.x,
                                gate * ho.y + (1.f - gate) * nfv.y,
                                gate * ho.z + (1.f - gate) * nfv.z,
                                gate * ho.w + (1.f - gate) * nfv.w);
        *(float4*)&out[(size_t)n * DD + lane * 4] = oo;
    }
}

// ---------------- launcher ----------------
extern "C" void kernel_launch(void* const* d_in, const int* in_sizes, int n_in,
                              void* d_out, int out_size)
{
    const float* nf   = (const float*)d_in[0];
    const float* ef   = (const float*)d_in[1];
    const int*   src  = (const int*)  d_in[2];
    const int*   dst  = (const int*)  d_in[3];
    const float* natt = (const float*)d_in[4];
    const float* relW = (const float*)d_in[5];
    const float* W1   = (const float*)d_in[6];
    const float* b1   = (const float*)d_in[7];
    const float* W2   = (const float*)d_in[8];
    const float* b2   = (const float*)d_in[9];
    const float* nfcW = (const float*)d_in[10];
    const float* nfcb = (const float*)d_in[11];
    const float* efcW = (const float*)d_in[12];
    const float* efcb = (const float*)d_in[13];
    const float* outW = (const float*)d_in[14];
    const float* outb = (const float*)d_in[15];
    const float* gW   = (const float*)d_in[16];
    const float* gb   = (const float*)d_in[17];
    float* out = (float*)d_out;

    static cudaStream_t s_side = nullptr;
    static cudaEvent_t e_fork = nullptr, e_prepF = nullptr, e_fill = nullptr, e_comb = nullptr;
    if (s_side == nullptr) {
        cudaStreamCreateWithFlags(&s_side, cudaStreamNonBlocking);
        cudaEventCreateWithFlags(&e_fork,  cudaEventDisableTiming);
        cudaEventCreateWithFlags(&e_prepF, cudaEventDisableTiming);
        cudaEventCreateWithFlags(&e_fill,  cudaEventDisableTiming);
        cudaEventCreateWithFlags(&e_comb,  cudaEventDisableTiming);
    }

    void* pDeg;
    cudaGetSymbolAddress(&pDeg, g_deg);

    cudaFuncSetAttribute(k_node_fc, cudaFuncAttributeMaxDynamicSharedMemorySize, SMEM_NFC);
    cudaFuncSetAttribute(k_mlp,     cudaFuncAttributeMaxDynamicSharedMemorySize, SMEM_MLP);
    cudaFuncSetAttribute(k_final,   cudaFuncAttributeMaxDynamicSharedMemorySize, SMEM_FIN);

    // fork: prepF + CSR build + combine on side stream
    cudaEventRecord(e_fork, 0);
    cudaStreamWaitEvent(s_side, e_fork, 0);
    k_prepF<<<192, 128, 0, s_side>>>(efcW, efcb, W1, b1);
    cudaEventRecord(e_prepF, s_side);
    cudaMemsetAsync(pDeg, 0, NN * sizeof(int), s_side);
    k_hist<<<(EE + 255) / 256, 256, 0, s_side>>>(dst);
    k_scan<<<1, 1024, 0, s_side>>>();
    k_fill<<<(EE + 255) / 256, 256, 0, s_side>>>(src, dst);
    cudaEventRecord(e_fill, s_side);
    k_combine<<<512, 128, 0, s_side>>>(natt, relW, outW);
    cudaEventRecord(e_comb, s_side);

    // main chain
    k_prepW<<<128, 128>>>(nfcW);
    k_node_fc<<<(NN + 127) / 128, 256, SMEM_NFC>>>(nf, nfcb);
    cudaStreamWaitEvent(0, e_prepF, 0);
    k_mlp<<<GRID_MLP, 768, SMEM_MLP>>>(ef, W2, b2);

    // join: gather needs CSR + mlp + h; final needs combine
    cudaStreamWaitEvent(0, e_fill, 0);
    k_gather<<<(NN + 7) / 8, 256>>>();
    cudaStreamWaitEvent(0, e_comb, 0);
    k_final<<<(NN + NB - 1) / NB, 256, SMEM_FIN>>>(nf, outb, gW, gb, out);
}